// round 8
// baseline (speedup 1.0000x reference)
#include <cuda_runtime.h>
#include <cuda_bf16.h>
#include <cuda_fp16.h>
#include <cstdint>

#define B_  32
#define T_  256
#define C_  2048
#define H_  16
#define D_  128
#define M_TOT (B_*T_)     // 8192
#define BH_  (B_*H_)      // 512

// ------------------------------------------------------------------
// Device globals
// ------------------------------------------------------------------
__device__ float g_q[(size_t)BH_*T_*D_];
__device__ float g_k[(size_t)BH_*T_*D_];
__device__ float g_cos[T_*64];
__device__ float g_sin[T_*64];
__device__ __half g_x16[(size_t)M_TOT*C_];
__device__ __half g_w16[(size_t)4*C_*C_];
__device__ __half g_y16[(size_t)M_TOT*C_];
__device__ __half g_q16[(size_t)BH_*T_*D_];
__device__ __half g_k16[(size_t)BH_*T_*D_];
__device__ __half g_v16[(size_t)BH_*T_*D_];
__device__ __half g_s16[(size_t)BH_*T_*T_];
__device__ __half g_p16[(size_t)BH_*T_*T_];

// ------------------------------------------------------------------
// PTX helpers
// ------------------------------------------------------------------
__device__ __forceinline__ uint32_t smem_u32(const void* p) {
    uint32_t a;
    asm("{ .reg .u64 t; cvta.to.shared.u64 t, %1; cvt.u32.u64 %0, t; }" : "=r"(a) : "l"(p));
    return a;
}
__device__ __forceinline__ void cp16(uint32_t dst, const void* src) {
    asm volatile("cp.async.cg.shared.global [%0], [%1], 16;" :: "r"(dst), "l"(src));
}
__device__ __forceinline__ void cp_commit() {
    asm volatile("cp.async.commit_group;" ::: "memory");
}
__device__ __forceinline__ void ldmx4(uint32_t* r, uint32_t addr) {
    asm volatile("ldmatrix.sync.aligned.m8n8.x4.shared.b16 {%0,%1,%2,%3}, [%4];"
                 : "=r"(r[0]), "=r"(r[1]), "=r"(r[2]), "=r"(r[3]) : "r"(addr));
}
__device__ __forceinline__ void ldmx4t(uint32_t* r, uint32_t addr) {
    asm volatile("ldmatrix.sync.aligned.m8n8.x4.trans.shared.b16 {%0,%1,%2,%3}, [%4];"
                 : "=r"(r[0]), "=r"(r[1]), "=r"(r[2]), "=r"(r[3]) : "r"(addr));
}
__device__ __forceinline__ void mma16816h(float* d, const uint32_t* a, const uint32_t* b) {
    asm volatile(
        "mma.sync.aligned.m16n8k16.row.col.f32.f16.f16.f32 "
        "{%0,%1,%2,%3}, {%4,%5,%6,%7}, {%8,%9}, {%0,%1,%2,%3};"
        : "+f"(d[0]), "+f"(d[1]), "+f"(d[2]), "+f"(d[3])
        : "r"(a[0]), "r"(a[1]), "r"(a[2]), "r"(a[3]), "r"(b[0]), "r"(b[1]));
}
// Swizzle for [rows][32 x 16-bit] tiles (64B rows)
__device__ __forceinline__ uint32_t swz(int r, int c) {
    return (uint32_t)(r * 64 + ((c ^ ((r >> 1) & 3)) << 4));
}
// Swizzle for [rows][64 x 16-bit] tiles (128B rows)
__device__ __forceinline__ uint32_t swz128(int r, int c) {
    return (uint32_t)(r * 128 + ((c ^ (r & 7)) << 4));
}

#define SCALE 0.08838834764831845f

// ------------------------------------------------------------------
// fp32 -> fp16 conversion
// ------------------------------------------------------------------
__global__ __launch_bounds__(256)
void split16_kernel(const float4* __restrict__ src, int dst_sel, int n4)
{
    int i = blockIdx.x * 256 + threadIdx.x;
    if (i >= n4) return;
    __half* dst = (dst_sel == 0) ? g_x16 : (g_w16 + (size_t)(dst_sel - 1) * C_ * C_);
    float4 v = src[i];
    __half2* dp = (__half2*)dst;
    dp[2*i]   = __floats2half2_rn(v.x, v.y);
    dp[2*i+1] = __floats2half2_rn(v.z, v.w);
}

// ------------------------------------------------------------------
// fp16 HMMA GEMM. CTA tile 128(M)x256(N), BK=64, 4 stages, 256 thr.
// 8 warps in 2(M) x 4(N) grid of 64x64 tiles. 1 CTA/SM, 192KB smem.
// mode 1: g_x16 @ g_w16[z]^T -> Q/K fp32, V fp16 ([B,H,T,D])
// mode 0: g_y16 @ g_w16[3]^T -> Out fp32 [M, C]
// ------------------------------------------------------------------
#define G16_STAGE 49152             // A 16KB | B 32KB
#define G16_SMEM (1024 + 4*G16_STAGE)

__global__ __launch_bounds__(256, 1)
void gemm16(float* __restrict__ Out, int mode)
{
    extern __shared__ char dsm[];
    const int tid  = threadIdx.x;
    const int wid  = tid >> 5;
    const int lane = tid & 31;
    const int bn = blockIdx.x * 256;
    const int bm = blockIdx.y * 128;
    const int wz = blockIdx.z;

    const __half* A_g = (mode == 0) ? g_y16 : g_x16;
    const int widx = (mode == 0) ? 3 : wz;
    const __half* B_g = g_w16 + (size_t)widx * C_ * C_;

    const uint32_t base = (smem_u32(dsm) + 1023u) & ~1023u;

    auto load_stage = [&](int kt, int s) {
        const uint32_t sb = base + (uint32_t)s * G16_STAGE;
        const int kb = kt * 64;
        #pragma unroll
        for (int it = 0; it < 4; it++) {           // A: 1024 chunks
            int idx = tid + it * 256;
            int r = idx >> 3, c = idx & 7;
            cp16(sb + swz128(r, c), A_g + (size_t)(bm + r) * C_ + kb + c * 8);
        }
        #pragma unroll
        for (int it = 0; it < 8; it++) {           // B: 2048 chunks
            int idx = tid + it * 256;
            int r = idx >> 3, c = idx & 7;
            cp16(sb + 16384 + swz128(r, c), B_g + (size_t)(bn + r) * C_ + kb + c * 8);
        }
        cp_commit();
    };

    // 2(M) x 4(N) warp grid of 64x64 tiles
    const int wm = (wid >> 2) * 64;
    const int wn = (wid & 3) * 64;
    const int arow = wm + (lane & 15);
    const int acol_base = (lane >> 4);
    const int brow = wn + (lane & 7) + ((lane & 16) >> 1);
    const int bcol_base = ((lane >> 3) & 1);

    float acc[4][8][4];
    #pragma unroll
    for (int i = 0; i < 4; i++)
        #pragma unroll
        for (int j = 0; j < 8; j++)
            #pragma unroll
            for (int q = 0; q < 4; q++) acc[i][j][q] = 0.0f;

    const int NK = C_ / 64;    // 32

    load_stage(0, 0);
    load_stage(1, 1);
    load_stage(2, 2);

    for (int c = 0; c < NK; c++) {
        __syncthreads();                      // consumers done with slot being refilled
        if (c + 3 < NK) load_stage(c + 3, (c + 3) & 3);
        else            cp_commit();
        asm volatile("cp.async.wait_group 3;" ::: "memory");
        __syncthreads();                      // stage c visible to all warps

        const uint32_t sA = base + (uint32_t)(c & 3) * G16_STAGE;
        const uint32_t sB = sA + 16384;

        #pragma unroll
        for (int ks = 0; ks < 4; ks++) {
            uint32_t ah[4][4];
            #pragma unroll
            for (int mt = 0; mt < 4; mt++)
                ldmx4(ah[mt], sA + swz128(arow + mt * 16, ks * 2 + acol_base));
            uint32_t bh[8][2];
            #pragma unroll
            for (int ng = 0; ng < 4; ng++) {
                uint32_t q[4];
                ldmx4(q, sB + swz128(brow + ng * 16, ks * 2 + bcol_base));
                bh[2*ng][0] = q[0]; bh[2*ng][1] = q[1];
                bh[2*ng+1][0] = q[2]; bh[2*ng+1][1] = q[3];
            }
            #pragma unroll
            for (int mt = 0; mt < 4; mt++)
                #pragma unroll
                for (int nt = 0; nt < 8; nt++)
                    mma16816h(acc[mt][nt], ah[mt], bh[nt]);
        }
    }

    float* qkv = (wz == 0) ? g_q : g_k;
    #pragma unroll
    for (int mt = 0; mt < 4; mt++) {
        const int row0 = bm + wm + mt * 16 + (lane >> 2);
        #pragma unroll
        for (int nt = 0; nt < 8; nt++) {
            const int col = bn + wn + nt * 8 + (lane & 3) * 2;
            #pragma unroll
            for (int half = 0; half < 2; half++) {
                const int row = row0 + half * 8;
                float y0 = acc[mt][nt][half * 2 + 0];
                float y1 = acc[mt][nt][half * 2 + 1];
                if (mode == 0) {
                    float2 v; v.x = y0; v.y = y1;
                    *(float2*)(Out + (size_t)row * C_ + col) = v;
                } else {
                    const int b = row >> 8, t = row & 255;
                    const int h = col >> 7, d0 = col & 127;
                    const size_t ix = (((size_t)b * H_ + h) * T_ + t) * D_ + d0;
                    if (wz < 2) {
                        float2 v; v.x = y0; v.y = y1;
                        *(float2*)(qkv + ix) = v;
                    } else {
                        *(__half2*)(g_v16 + ix) = __floats2half2_rn(y0, y1);
                    }
                }
            }
        }
    }
}

// ------------------------------------------------------------------
// RoPE tables + application (fp32 in, fp16 out)
// ------------------------------------------------------------------
__global__ void rope_table_kernel()
{
    int idx = blockIdx.x * blockDim.x + threadIdx.x;
    if (idx >= T_ * 64) return;
    int j = idx & 63;
    int t = idx >> 6;
    double inv = exp(-(double)j * (9.210340371976184 / 64.0));
    double th = (double)t * inv;
    g_cos[idx] = (float)cos(th);
    g_sin[idx] = (float)sin(th);
}

__global__ __launch_bounds__(256)
void rope_split_kernel()
{
    int idx = blockIdx.x * 256 + threadIdx.x;
    int j = idx & 63;
    int t = (idx >> 6) & 255;
    int rest = idx >> 14;
    int bh = rest & 511;
    int isK = rest >> 9;
    const float* src = (isK ? g_k : g_q) + ((size_t)bh * T_ + t) * D_ + j;
    float c = g_cos[t * 64 + j];
    float s = g_sin[t * 64 + j];
    float x0 = src[0], x1 = src[64];
    float r0 = x0 * c - x1 * s;
    float r1 = x1 * c + x0 * s;
    __half* dh = isK ? g_k16 : g_q16;
    const size_t bx = ((size_t)bh * T_ + t) * D_ + j;
    dh[bx]      = __float2half(r0);
    dh[bx + 64] = __float2half(r1);
}

// ------------------------------------------------------------------
// attn_qk: S = Q·K^T (fp16, causal tiles), S out fp16
// ------------------------------------------------------------------
#define QK_SMEM (1024 + 2*32768)

__global__ __launch_bounds__(256, 1)
void attn_qk()
{
    extern __shared__ char dsm[];
    const int tid  = threadIdx.x;
    const int wid  = tid >> 5;
    const int lane = tid & 31;
    const int pair = blockIdx.x;
    const int bh   = blockIdx.y;
    const int qt   = pair ? 1 : 0;
    const int kt   = (pair == 2) ? 1 : 0;

    const __half* Qg = g_q16 + ((size_t)bh * T_ + qt * 128) * D_;
    const __half* Kg = g_k16 + ((size_t)bh * T_ + kt * 128) * D_;

    const uint32_t base = (smem_u32(dsm) + 1023u) & ~1023u;

    #pragma unroll
    for (int it = 0; it < 8; it++) {
        int idx = tid + it * 256;
        int r = idx >> 4, d16 = idx & 15;
        int c = d16 >> 2, ic = d16 & 3;
        uint32_t off = (uint32_t)c * 8192 + swz(r, ic);
        size_t g = (size_t)r * D_ + d16 * 8;
        cp16(base + off,         Qg + g);
        cp16(base + 32768 + off, Kg + g);
    }
    cp_commit();
    asm volatile("cp.async.wait_group 0;" ::: "memory");
    __syncthreads();

    const int wm = (wid >> 1) * 32;
    const int wn = (wid & 1) * 64;
    const int arow = wm + (lane & 15);
    const int acol_base = (lane >> 4);
    const int brow = wn + (lane & 7) + ((lane & 16) >> 1);
    const int bcol_base = ((lane >> 3) & 1);

    float acc[2][8][4];
    #pragma unroll
    for (int i = 0; i < 2; i++)
        #pragma unroll
        for (int j = 0; j < 8; j++)
            #pragma unroll
            for (int q = 0; q < 4; q++) acc[i][j][q] = 0.0f;

    #pragma unroll
    for (int c = 0; c < 4; c++) {
        const uint32_t sA = base + (uint32_t)c * 8192;
        const uint32_t sB = sA + 32768;
        #pragma unroll
        for (int ks = 0; ks < 2; ks++) {
            uint32_t ah[2][4];
            #pragma unroll
            for (int mt = 0; mt < 2; mt++)
                ldmx4(ah[mt], sA + swz(arow + mt * 16, ks * 2 + acol_base));
            uint32_t bh_[8][2];
            #pragma unroll
            for (int ng = 0; ng < 4; ng++) {
                uint32_t q[4];
                ldmx4(q, sB + swz(brow + ng * 16, ks * 2 + bcol_base));
                bh_[2*ng][0] = q[0]; bh_[2*ng][1] = q[1];
                bh_[2*ng+1][0] = q[2]; bh_[2*ng+1][1] = q[3];
            }
            #pragma unroll
            for (int mt = 0; mt < 2; mt++)
                #pragma unroll
                for (int nt = 0; nt < 8; nt++)
                    mma16816h(acc[mt][nt], ah[mt], bh_[nt]);
        }
    }

    #pragma unroll
    for (int mt = 0; mt < 2; mt++) {
        const int row0 = wm + mt * 16 + (lane >> 2);
        #pragma unroll
        for (int nt = 0; nt < 8; nt++) {
            const int col = wn + nt * 8 + (lane & 3) * 2;
            #pragma unroll
            for (int half = 0; half < 2; half++) {
                const int row = row0 + half * 8;
                *(__half2*)(g_s16 + ((size_t)bh * T_ + qt * 128 + row) * T_ + kt * 128 + col) =
                    __floats2half2_rn(acc[mt][nt][half * 2 + 0], acc[mt][nt][half * 2 + 1]);
            }
        }
    }
}

// ------------------------------------------------------------------
// softmax_p: masked row softmax (fp16 in) -> P fp16 (zero-padded)
// ------------------------------------------------------------------
__global__ __launch_bounds__(256)
void softmax_p()
{
    const int warp = threadIdx.x >> 5;
    const int lane = threadIdx.x & 31;
    const int row = blockIdx.x * 8 + warp;
    const int bh = row >> 8;
    const int q  = row & 255;
    const size_t rb = ((size_t)bh * T_ + q) * T_;
    const int W = (q < 128) ? 128 : 256;
    const int n = W >> 5;

    float e[8];
    float m = -1e30f;
    #pragma unroll
    for (int i = 0; i < 8; i++) {
        if (i >= n) break;
        int k = lane + 32 * i;
        float v = (k <= q) ? __half2float(g_s16[rb + k]) * SCALE : -1e30f;
        e[i] = v;
        m = fmaxf(m, v);
    }
    #pragma unroll
    for (int o = 16; o > 0; o >>= 1) m = fmaxf(m, __shfl_xor_sync(0xffffffffu, m, o));
    float sum = 0.f;
    #pragma unroll
    for (int i = 0; i < 8; i++) {
        if (i >= n) break;
        float x = __expf(e[i] - m);
        e[i] = x;
        sum += x;
    }
    #pragma unroll
    for (int o = 16; o > 0; o >>= 1) sum += __shfl_xor_sync(0xffffffffu, sum, o);
    const float inv = 1.0f / sum;
    #pragma unroll
    for (int i = 0; i < 8; i++) {
        if (i >= n) break;
        int k = lane + 32 * i;
        g_p16[rb + k] = __float2half(e[i] * inv);
    }
}

// ------------------------------------------------------------------
// attn_pv: Y = P @ V (fp16); epilogue -> g_y16 [B,T,C]
// ------------------------------------------------------------------
#define PV_STAGE 16896   // P 8192 | V 8704
#define PV_SMEM  (1024 + 2*PV_STAGE)

__global__ __launch_bounds__(256, 1)
void attn_pv()
{
    extern __shared__ char dsm[];
    const int tid  = threadIdx.x;
    const int wid  = tid >> 5;
    const int lane = tid & 31;
    const int qt = blockIdx.x;
    const int bh = blockIdx.y;

    const uint32_t base = (smem_u32(dsm) + 1023u) & ~1023u;
    const size_t prow = ((size_t)bh * T_ + qt * 128) * T_;
    const size_t vrow = (size_t)bh * T_ * D_;

    auto load_stage = [&](int kc, int s) {
        const uint32_t sb = base + (uint32_t)s * PV_STAGE;
        const int kb = kc * 32;
        #pragma unroll
        for (int it = 0; it < 2; it++) {
            int idx = tid + it * 256;
            int r = idx >> 2, ic = idx & 3;
            cp16(sb + swz(r, ic), g_p16 + prow + (size_t)r * T_ + kb + ic * 8);
        }
        #pragma unroll
        for (int it = 0; it < 2; it++) {
            int idx = tid + it * 256;
            int r = idx >> 4, dc = idx & 15;
            cp16(sb + 8192 + (uint32_t)r * 272 + dc * 16,
                 g_v16 + vrow + (size_t)(kb + r) * D_ + dc * 8);
        }
        cp_commit();
    };

    const int wm = (wid >> 1) * 32;
    const int wn = (wid & 1) * 64;
    const int arow = wm + (lane & 15);
    const int acol_base = (lane >> 4);
    const int kl_part = ((lane >> 3) & 1) * 8 + (lane & 7);
    const int nblk = lane >> 4;

    float acc[2][8][4];
    #pragma unroll
    for (int i = 0; i < 2; i++)
        #pragma unroll
        for (int j = 0; j < 8; j++)
            #pragma unroll
            for (int q = 0; q < 4; q++) acc[i][j][q] = 0.0f;

    const int nc = (qt + 1) * 4;
    load_stage(0, 0);
    load_stage(1, 1);

    for (int kc = 0; kc < nc; kc++) {
        if (kc + 1 < nc) asm volatile("cp.async.wait_group 1;" ::: "memory");
        else             asm volatile("cp.async.wait_group 0;" ::: "memory");
        __syncthreads();

        const uint32_t sb = base + (uint32_t)(kc & 1) * PV_STAGE;
        const uint32_t sV = sb + 8192;

        #pragma unroll
        for (int ks = 0; ks < 2; ks++) {
            uint32_t ah[2][4];
            #pragma unroll
            for (int mt = 0; mt < 2; mt++)
                ldmx4(ah[mt], sb + swz(arow + mt * 16, ks * 2 + acol_base));
            uint32_t bh_[8][2];
            #pragma unroll
            for (int dp = 0; dp < 4; dp++) {
                const uint32_t addr = sV + (uint32_t)(ks * 16 + kl_part) * 272
                                    + (uint32_t)((wn >> 3) + dp * 2 + nblk) * 16;
                uint32_t q[4];
                ldmx4t(q, addr);
                bh_[2*dp][0] = q[0]; bh_[2*dp][1] = q[1];
                bh_[2*dp+1][0] = q[2]; bh_[2*dp+1][1] = q[3];
            }
            #pragma unroll
            for (int mt = 0; mt < 2; mt++)
                #pragma unroll
                for (int nt = 0; nt < 8; nt++)
                    mma16816h(acc[mt][nt], ah[mt], bh_[nt]);
        }
        __syncthreads();
        if (kc + 2 < nc) load_stage(kc + 2, kc & 1);
    }

    const int b = bh >> 4, h = bh & 15;
    #pragma unroll
    for (int mt = 0; mt < 2; mt++) {
        const int row0 = qt * 128 + wm + mt * 16 + (lane >> 2);
        #pragma unroll
        for (int nt = 0; nt < 8; nt++) {
            const int d = wn + nt * 8 + (lane & 3) * 2;
            #pragma unroll
            for (int half = 0; half < 2; half++) {
                const int t = row0 + half * 8;
                const size_t ix = ((size_t)b * T_ + t) * C_ + h * D_ + d;
                *(__half2*)(g_y16 + ix) =
                    __floats2half2_rn(acc[mt][nt][half * 2 + 0], acc[mt][nt][half * 2 + 1]);
            }
        }
    }
}

// ------------------------------------------------------------------
extern "C" void kernel_launch(void* const* d_in, const int* in_sizes, int n_in,
                              void* d_out, int out_size)
{
    const float* x  = (const float*)d_in[0];
    const float* wq = (const float*)d_in[1];
    const float* wk = (const float*)d_in[2];
    const float* wv = (const float*)d_in[3];
    const float* wo = (const float*)d_in[4];
    float* out = (float*)d_out;

    const int nx4 = M_TOT * C_ / 4;
    const int nw4 = C_ * C_ / 4;

    cudaFuncSetAttribute(gemm16,  cudaFuncAttributeMaxDynamicSharedMemorySize, G16_SMEM);
    cudaFuncSetAttribute(attn_qk, cudaFuncAttributeMaxDynamicSharedMemorySize, QK_SMEM);
    cudaFuncSetAttribute(attn_pv, cudaFuncAttributeMaxDynamicSharedMemorySize, PV_SMEM);

    // Launches 1-4: splits needed for QKV GEMM (gemm16 is launch #5 -> ncu target)
    split16_kernel<<<(nx4 + 255)/256, 256>>>((const float4*)x,  0, nx4);
    split16_kernel<<<(nw4 + 255)/256, 256>>>((const float4*)wq, 1, nw4);
    split16_kernel<<<(nw4 + 255)/256, 256>>>((const float4*)wk, 2, nw4);
    split16_kernel<<<(nw4 + 255)/256, 256>>>((const float4*)wv, 3, nw4);

    // QKV projections (fp16 HMMA, 128x256 CTA tile)
    gemm16<<<dim3(C_/256, M_TOT/128, 3), 256, G16_SMEM>>>(nullptr, 1);

    // RoPE -> fp16 Q,K
    rope_table_kernel<<<(T_*64 + 255)/256, 256>>>();
    rope_split_kernel<<<(2 * BH_ * T_ * 64) / 256, 256>>>();

    // wo split (only needed by the final GEMM)
    split16_kernel<<<(nw4 + 255)/256, 256>>>((const float4*)wo, 4, nw4);

    // Attention
    attn_qk<<<dim3(3, BH_), 256, QK_SMEM>>>();
    softmax_p<<<(BH_ * T_) / 8, 256>>>();
    attn_pv<<<dim3(2, BH_), 256, PV_SMEM>>>();

    // Output projection
    gemm16<<<dim3(C_/256, M_TOT/128, 1), 256, G16_SMEM>>>(out, 0);
}

// round 9
// speedup vs baseline: 1.1039x; 1.1039x over previous
#include <cuda_runtime.h>
#include <cuda_bf16.h>
#include <cuda_fp16.h>
#include <cstdint>

#define B_  32
#define T_  256
#define C_  2048
#define H_  16
#define D_  128
#define M_TOT (B_*T_)     // 8192
#define BH_  (B_*H_)      // 512

// ------------------------------------------------------------------
// Device globals
// ------------------------------------------------------------------
__device__ float g_q[(size_t)BH_*T_*D_];
__device__ float g_k[(size_t)BH_*T_*D_];
__device__ float g_cos[T_*64];
__device__ float g_sin[T_*64];
__device__ __half g_x16[(size_t)M_TOT*C_];
__device__ __half g_w16[(size_t)4*C_*C_];
__device__ __half g_y16[(size_t)M_TOT*C_];
__device__ __half g_q16[(size_t)BH_*T_*D_];
__device__ __half g_k16[(size_t)BH_*T_*D_];
__device__ __half g_v16[(size_t)BH_*T_*D_];
__device__ __half g_s16[(size_t)BH_*T_*T_];
__device__ __half g_p16[(size_t)BH_*T_*T_];

// ------------------------------------------------------------------
// PTX helpers
// ------------------------------------------------------------------
__device__ __forceinline__ uint32_t smem_u32(const void* p) {
    uint32_t a;
    asm("{ .reg .u64 t; cvta.to.shared.u64 t, %1; cvt.u32.u64 %0, t; }" : "=r"(a) : "l"(p));
    return a;
}
__device__ __forceinline__ void cp16(uint32_t dst, const void* src) {
    asm volatile("cp.async.cg.shared.global [%0], [%1], 16;" :: "r"(dst), "l"(src));
}
__device__ __forceinline__ void cp_commit() {
    asm volatile("cp.async.commit_group;" ::: "memory");
}
__device__ __forceinline__ void ldmx4(uint32_t* r, uint32_t addr) {
    asm volatile("ldmatrix.sync.aligned.m8n8.x4.shared.b16 {%0,%1,%2,%3}, [%4];"
                 : "=r"(r[0]), "=r"(r[1]), "=r"(r[2]), "=r"(r[3]) : "r"(addr));
}
__device__ __forceinline__ void ldmx4t(uint32_t* r, uint32_t addr) {
    asm volatile("ldmatrix.sync.aligned.m8n8.x4.trans.shared.b16 {%0,%1,%2,%3}, [%4];"
                 : "=r"(r[0]), "=r"(r[1]), "=r"(r[2]), "=r"(r[3]) : "r"(addr));
}
__device__ __forceinline__ void mma16816h(float* d, const uint32_t* a, const uint32_t* b) {
    asm volatile(
        "mma.sync.aligned.m16n8k16.row.col.f32.f16.f16.f32 "
        "{%0,%1,%2,%3}, {%4,%5,%6,%7}, {%8,%9}, {%0,%1,%2,%3};"
        : "+f"(d[0]), "+f"(d[1]), "+f"(d[2]), "+f"(d[3])
        : "r"(a[0]), "r"(a[1]), "r"(a[2]), "r"(a[3]), "r"(b[0]), "r"(b[1]));
}
// Swizzle for [rows][32 x 16-bit] tiles (64B rows)
__device__ __forceinline__ uint32_t swz(int r, int c) {
    return (uint32_t)(r * 64 + ((c ^ ((r >> 1) & 3)) << 4));
}
// Swizzle for [rows][64 x 16-bit] tiles (128B rows)
__device__ __forceinline__ uint32_t swz128(int r, int c) {
    return (uint32_t)(r * 128 + ((c ^ (r & 7)) << 4));
}

#define SCALE 0.08838834764831845f

// ------------------------------------------------------------------
// fp32 -> fp16 conversion
// ------------------------------------------------------------------
__global__ __launch_bounds__(256)
void split16_kernel(const float4* __restrict__ src, int dst_sel, int n4)
{
    int i = blockIdx.x * 256 + threadIdx.x;
    if (i >= n4) return;
    __half* dst = (dst_sel == 0) ? g_x16 : (g_w16 + (size_t)(dst_sel - 1) * C_ * C_);
    float4 v = src[i];
    __half2* dp = (__half2*)dst;
    dp[2*i]   = __floats2half2_rn(v.x, v.y);
    dp[2*i+1] = __floats2half2_rn(v.z, v.w);
}

// ------------------------------------------------------------------
// fp16 HMMA GEMM. CTA 128x128, BK=64, 3 stages, 128 thr, 2 CTA/SM.
// 4 warps, 64x64 tiles. SINGLE __syncthreads per K-chunk.
// mode 1: g_x16 @ g_w16[z]^T -> Q/K fp32, V fp16 ([B,H,T,D])
// mode 0: g_y16 @ g_w16[3]^T -> Out fp32 [M, C]
// ------------------------------------------------------------------
#define G16_STAGE 32768             // A 16KB | B 16KB
#define G16_SMEM (1024 + 3*G16_STAGE)

__global__ __launch_bounds__(128, 2)
void gemm16(float* __restrict__ Out, int mode)
{
    extern __shared__ char dsm[];
    const int tid  = threadIdx.x;
    const int wid  = tid >> 5;
    const int lane = tid & 31;
    const int bn = blockIdx.x * 128;
    const int bm = blockIdx.y * 128;
    const int wz = blockIdx.z;

    const __half* A_g = (mode == 0) ? g_y16 : g_x16;
    const int widx = (mode == 0) ? 3 : wz;
    const __half* B_g = g_w16 + (size_t)widx * C_ * C_;

    const uint32_t base = (smem_u32(dsm) + 1023u) & ~1023u;

    auto load_stage = [&](int kt, int s) {
        const uint32_t sb = base + (uint32_t)s * G16_STAGE;
        const int kb = kt * 64;
        #pragma unroll
        for (int it = 0; it < 8; it++) {
            int idx = tid + it * 128;          // 0..1023
            int r = idx >> 3, c = idx & 7;
            uint32_t off = swz128(r, c);
            cp16(sb + off,         A_g + (size_t)(bm + r) * C_ + kb + c * 8);
            cp16(sb + 16384 + off, B_g + (size_t)(bn + r) * C_ + kb + c * 8);
        }
        cp_commit();
    };

    // 2x2 warp grid of 64x64 tiles
    const int wm = (wid >> 1) * 64;
    const int wn = (wid & 1) * 64;
    const int arow = wm + (lane & 15);
    const int acol_base = (lane >> 4);
    const int brow = wn + (lane & 7) + ((lane & 16) >> 1);
    const int bcol_base = ((lane >> 3) & 1);

    float acc[4][8][4];
    #pragma unroll
    for (int i = 0; i < 4; i++)
        #pragma unroll
        for (int j = 0; j < 8; j++)
            #pragma unroll
            for (int q = 0; q < 4; q++) acc[i][j][q] = 0.0f;

    const int NK = C_ / 64;    // 32

    load_stage(0, 0);          // group for stage 0
    load_stage(1, 1);          // group for stage 1

    // Invariant: one commit per iteration. Before wait at iter c, the last
    // 1 committed group is stage c+1 (iter c-1); wait_group 1 => stage c done.
    // The single sync also proves all warps finished compute c-1, so the slot
    // (c+2)%3 == (c-1)%3 is safe to refill after it.
    for (int c = 0; c < NK; c++) {
        asm volatile("cp.async.wait_group 1;" ::: "memory");
        __syncthreads();
        if (c + 2 < NK) load_stage(c + 2, (c + 2) % 3);
        else            cp_commit();          // empty group keeps accounting

        const uint32_t sA = base + (uint32_t)(c % 3) * G16_STAGE;
        const uint32_t sB = sA + 16384;

        #pragma unroll
        for (int ks = 0; ks < 4; ks++) {
            uint32_t ah[4][4];
            #pragma unroll
            for (int mt = 0; mt < 4; mt++)
                ldmx4(ah[mt], sA + swz128(arow + mt * 16, ks * 2 + acol_base));
            uint32_t bh[8][2];
            #pragma unroll
            for (int ng = 0; ng < 4; ng++) {
                uint32_t q[4];
                ldmx4(q, sB + swz128(brow + ng * 16, ks * 2 + bcol_base));
                bh[2*ng][0] = q[0]; bh[2*ng][1] = q[1];
                bh[2*ng+1][0] = q[2]; bh[2*ng+1][1] = q[3];
            }
            #pragma unroll
            for (int mt = 0; mt < 4; mt++)
                #pragma unroll
                for (int nt = 0; nt < 8; nt++)
                    mma16816h(acc[mt][nt], ah[mt], bh[nt]);
        }
    }

    float* qkv = (wz == 0) ? g_q : g_k;
    #pragma unroll
    for (int mt = 0; mt < 4; mt++) {
        const int row0 = bm + wm + mt * 16 + (lane >> 2);
        #pragma unroll
        for (int nt = 0; nt < 8; nt++) {
            const int col = bn + wn + nt * 8 + (lane & 3) * 2;
            #pragma unroll
            for (int half = 0; half < 2; half++) {
                const int row = row0 + half * 8;
                float y0 = acc[mt][nt][half * 2 + 0];
                float y1 = acc[mt][nt][half * 2 + 1];
                if (mode == 0) {
                    float2 v; v.x = y0; v.y = y1;
                    *(float2*)(Out + (size_t)row * C_ + col) = v;
                } else {
                    const int b = row >> 8, t = row & 255;
                    const int h = col >> 7, d0 = col & 127;
                    const size_t ix = (((size_t)b * H_ + h) * T_ + t) * D_ + d0;
                    if (wz < 2) {
                        float2 v; v.x = y0; v.y = y1;
                        *(float2*)(qkv + ix) = v;
                    } else {
                        *(__half2*)(g_v16 + ix) = __floats2half2_rn(y0, y1);
                    }
                }
            }
        }
    }
}

// ------------------------------------------------------------------
// RoPE tables + application (fp32 in, fp16 out)
// ------------------------------------------------------------------
__global__ void rope_table_kernel()
{
    int idx = blockIdx.x * blockDim.x + threadIdx.x;
    if (idx >= T_ * 64) return;
    int j = idx & 63;
    int t = idx >> 6;
    double inv = exp(-(double)j * (9.210340371976184 / 64.0));
    double th = (double)t * inv;
    g_cos[idx] = (float)cos(th);
    g_sin[idx] = (float)sin(th);
}

__global__ __launch_bounds__(256)
void rope_split_kernel()
{
    int idx = blockIdx.x * 256 + threadIdx.x;
    int j = idx & 63;
    int t = (idx >> 6) & 255;
    int rest = idx >> 14;
    int bh = rest & 511;
    int isK = rest >> 9;
    const float* src = (isK ? g_k : g_q) + ((size_t)bh * T_ + t) * D_ + j;
    float c = g_cos[t * 64 + j];
    float s = g_sin[t * 64 + j];
    float x0 = src[0], x1 = src[64];
    float r0 = x0 * c - x1 * s;
    float r1 = x1 * c + x0 * s;
    __half* dh = isK ? g_k16 : g_q16;
    const size_t bx = ((size_t)bh * T_ + t) * D_ + j;
    dh[bx]      = __float2half(r0);
    dh[bx + 64] = __float2half(r1);
}

// ------------------------------------------------------------------
// attn_qk: S = Q·K^T (fp16, causal tiles), S out fp16
// ------------------------------------------------------------------
#define QK_SMEM (1024 + 2*32768)

__global__ __launch_bounds__(256, 1)
void attn_qk()
{
    extern __shared__ char dsm[];
    const int tid  = threadIdx.x;
    const int wid  = tid >> 5;
    const int lane = tid & 31;
    const int pair = blockIdx.x;
    const int bh   = blockIdx.y;
    const int qt   = pair ? 1 : 0;
    const int kt   = (pair == 2) ? 1 : 0;

    const __half* Qg = g_q16 + ((size_t)bh * T_ + qt * 128) * D_;
    const __half* Kg = g_k16 + ((size_t)bh * T_ + kt * 128) * D_;

    const uint32_t base = (smem_u32(dsm) + 1023u) & ~1023u;

    #pragma unroll
    for (int it = 0; it < 8; it++) {
        int idx = tid + it * 256;
        int r = idx >> 4, d16 = idx & 15;
        int c = d16 >> 2, ic = d16 & 3;
        uint32_t off = (uint32_t)c * 8192 + swz(r, ic);
        size_t g = (size_t)r * D_ + d16 * 8;
        cp16(base + off,         Qg + g);
        cp16(base + 32768 + off, Kg + g);
    }
    cp_commit();
    asm volatile("cp.async.wait_group 0;" ::: "memory");
    __syncthreads();

    const int wm = (wid >> 1) * 32;
    const int wn = (wid & 1) * 64;
    const int arow = wm + (lane & 15);
    const int acol_base = (lane >> 4);
    const int brow = wn + (lane & 7) + ((lane & 16) >> 1);
    const int bcol_base = ((lane >> 3) & 1);

    float acc[2][8][4];
    #pragma unroll
    for (int i = 0; i < 2; i++)
        #pragma unroll
        for (int j = 0; j < 8; j++)
            #pragma unroll
            for (int q = 0; q < 4; q++) acc[i][j][q] = 0.0f;

    #pragma unroll
    for (int c = 0; c < 4; c++) {
        const uint32_t sA = base + (uint32_t)c * 8192;
        const uint32_t sB = sA + 32768;
        #pragma unroll
        for (int ks = 0; ks < 2; ks++) {
            uint32_t ah[2][4];
            #pragma unroll
            for (int mt = 0; mt < 2; mt++)
                ldmx4(ah[mt], sA + swz(arow + mt * 16, ks * 2 + acol_base));
            uint32_t bh_[8][2];
            #pragma unroll
            for (int ng = 0; ng < 4; ng++) {
                uint32_t q[4];
                ldmx4(q, sB + swz(brow + ng * 16, ks * 2 + bcol_base));
                bh_[2*ng][0] = q[0]; bh_[2*ng][1] = q[1];
                bh_[2*ng+1][0] = q[2]; bh_[2*ng+1][1] = q[3];
            }
            #pragma unroll
            for (int mt = 0; mt < 2; mt++)
                #pragma unroll
                for (int nt = 0; nt < 8; nt++)
                    mma16816h(acc[mt][nt], ah[mt], bh_[nt]);
        }
    }

    #pragma unroll
    for (int mt = 0; mt < 2; mt++) {
        const int row0 = wm + mt * 16 + (lane >> 2);
        #pragma unroll
        for (int nt = 0; nt < 8; nt++) {
            const int col = wn + nt * 8 + (lane & 3) * 2;
            #pragma unroll
            for (int half = 0; half < 2; half++) {
                const int row = row0 + half * 8;
                *(__half2*)(g_s16 + ((size_t)bh * T_ + qt * 128 + row) * T_ + kt * 128 + col) =
                    __floats2half2_rn(acc[mt][nt][half * 2 + 0], acc[mt][nt][half * 2 + 1]);
            }
        }
    }
}

// ------------------------------------------------------------------
// softmax_p: masked row softmax (fp16 in) -> P fp16 (zero-padded)
// ------------------------------------------------------------------
__global__ __launch_bounds__(256)
void softmax_p()
{
    const int warp = threadIdx.x >> 5;
    const int lane = threadIdx.x & 31;
    const int row = blockIdx.x * 8 + warp;
    const int bh = row >> 8;
    const int q  = row & 255;
    const size_t rb = ((size_t)bh * T_ + q) * T_;
    const int W = (q < 128) ? 128 : 256;
    const int n = W >> 5;

    float e[8];
    float m = -1e30f;
    #pragma unroll
    for (int i = 0; i < 8; i++) {
        if (i >= n) break;
        int k = lane + 32 * i;
        float v = (k <= q) ? __half2float(g_s16[rb + k]) * SCALE : -1e30f;
        e[i] = v;
        m = fmaxf(m, v);
    }
    #pragma unroll
    for (int o = 16; o > 0; o >>= 1) m = fmaxf(m, __shfl_xor_sync(0xffffffffu, m, o));
    float sum = 0.f;
    #pragma unroll
    for (int i = 0; i < 8; i++) {
        if (i >= n) break;
        float x = __expf(e[i] - m);
        e[i] = x;
        sum += x;
    }
    #pragma unroll
    for (int o = 16; o > 0; o >>= 1) sum += __shfl_xor_sync(0xffffffffu, sum, o);
    const float inv = 1.0f / sum;
    #pragma unroll
    for (int i = 0; i < 8; i++) {
        if (i >= n) break;
        int k = lane + 32 * i;
        g_p16[rb + k] = __float2half(e[i] * inv);
    }
}

// ------------------------------------------------------------------
// attn_pv: Y = P @ V (fp16); epilogue -> g_y16 [B,T,C]
// ------------------------------------------------------------------
#define PV_STAGE 16896   // P 8192 | V 8704
#define PV_SMEM  (1024 + 2*PV_STAGE)

__global__ __launch_bounds__(256, 1)
void attn_pv()
{
    extern __shared__ char dsm[];
    const int tid  = threadIdx.x;
    const int wid  = tid >> 5;
    const int lane = tid & 31;
    const int qt = blockIdx.x;
    const int bh = blockIdx.y;

    const uint32_t base = (smem_u32(dsm) + 1023u) & ~1023u;
    const size_t prow = ((size_t)bh * T_ + qt * 128) * T_;
    const size_t vrow = (size_t)bh * T_ * D_;

    auto load_stage = [&](int kc, int s) {
        const uint32_t sb = base + (uint32_t)s * PV_STAGE;
        const int kb = kc * 32;
        #pragma unroll
        for (int it = 0; it < 2; it++) {
            int idx = tid + it * 256;
            int r = idx >> 2, ic = idx & 3;
            cp16(sb + swz(r, ic), g_p16 + prow + (size_t)r * T_ + kb + ic * 8);
        }
        #pragma unroll
        for (int it = 0; it < 2; it++) {
            int idx = tid + it * 256;
            int r = idx >> 4, dc = idx & 15;
            cp16(sb + 8192 + (uint32_t)r * 272 + dc * 16,
                 g_v16 + vrow + (size_t)(kb + r) * D_ + dc * 8);
        }
        cp_commit();
    };

    const int wm = (wid >> 1) * 32;
    const int wn = (wid & 1) * 64;
    const int arow = wm + (lane & 15);
    const int acol_base = (lane >> 4);
    const int kl_part = ((lane >> 3) & 1) * 8 + (lane & 7);
    const int nblk = lane >> 4;

    float acc[2][8][4];
    #pragma unroll
    for (int i = 0; i < 2; i++)
        #pragma unroll
        for (int j = 0; j < 8; j++)
            #pragma unroll
            for (int q = 0; q < 4; q++) acc[i][j][q] = 0.0f;

    const int nc = (qt + 1) * 4;
    load_stage(0, 0);
    load_stage(1, 1);

    for (int kc = 0; kc < nc; kc++) {
        if (kc + 1 < nc) asm volatile("cp.async.wait_group 1;" ::: "memory");
        else             asm volatile("cp.async.wait_group 0;" ::: "memory");
        __syncthreads();

        const uint32_t sb = base + (uint32_t)(kc & 1) * PV_STAGE;
        const uint32_t sV = sb + 8192;

        #pragma unroll
        for (int ks = 0; ks < 2; ks++) {
            uint32_t ah[2][4];
            #pragma unroll
            for (int mt = 0; mt < 2; mt++)
                ldmx4(ah[mt], sb + swz(arow + mt * 16, ks * 2 + acol_base));
            uint32_t bh_[8][2];
            #pragma unroll
            for (int dp = 0; dp < 4; dp++) {
                const uint32_t addr = sV + (uint32_t)(ks * 16 + kl_part) * 272
                                    + (uint32_t)((wn >> 3) + dp * 2 + nblk) * 16;
                uint32_t q[4];
                ldmx4t(q, addr);
                bh_[2*dp][0] = q[0]; bh_[2*dp][1] = q[1];
                bh_[2*dp+1][0] = q[2]; bh_[2*dp+1][1] = q[3];
            }
            #pragma unroll
            for (int mt = 0; mt < 2; mt++)
                #pragma unroll
                for (int nt = 0; nt < 8; nt++)
                    mma16816h(acc[mt][nt], ah[mt], bh_[nt]);
        }
        __syncthreads();
        if (kc + 2 < nc) load_stage(kc + 2, kc & 1);
    }

    const int b = bh >> 4, h = bh & 15;
    #pragma unroll
    for (int mt = 0; mt < 2; mt++) {
        const int row0 = qt * 128 + wm + mt * 16 + (lane >> 2);
        #pragma unroll
        for (int nt = 0; nt < 8; nt++) {
            const int d = wn + nt * 8 + (lane & 3) * 2;
            #pragma unroll
            for (int half = 0; half < 2; half++) {
                const int t = row0 + half * 8;
                const size_t ix = ((size_t)b * T_ + t) * C_ + h * D_ + d;
                *(__half2*)(g_y16 + ix) =
                    __floats2half2_rn(acc[mt][nt][half * 2 + 0], acc[mt][nt][half * 2 + 1]);
            }
        }
    }
}

// ------------------------------------------------------------------
extern "C" void kernel_launch(void* const* d_in, const int* in_sizes, int n_in,
                              void* d_out, int out_size)
{
    const float* x  = (const float*)d_in[0];
    const float* wq = (const float*)d_in[1];
    const float* wk = (const float*)d_in[2];
    const float* wv = (const float*)d_in[3];
    const float* wo = (const float*)d_in[4];
    float* out = (float*)d_out;

    const int nx4 = M_TOT * C_ / 4;
    const int nw4 = C_ * C_ / 4;

    cudaFuncSetAttribute(gemm16,  cudaFuncAttributeMaxDynamicSharedMemorySize, G16_SMEM);
    cudaFuncSetAttribute(attn_qk, cudaFuncAttributeMaxDynamicSharedMemorySize, QK_SMEM);
    cudaFuncSetAttribute(attn_pv, cudaFuncAttributeMaxDynamicSharedMemorySize, PV_SMEM);

    // Launches 1-5 (ncu -s 5 skips these; #6 = gemm16)
    split16_kernel<<<(nx4 + 255)/256, 256>>>((const float4*)x,  0, nx4);
    split16_kernel<<<(nw4 + 255)/256, 256>>>((const float4*)wq, 1, nw4);
    split16_kernel<<<(nw4 + 255)/256, 256>>>((const float4*)wk, 2, nw4);
    split16_kernel<<<(nw4 + 255)/256, 256>>>((const float4*)wv, 3, nw4);
    rope_table_kernel<<<(T_*64 + 255)/256, 256>>>();

    // QKV projections (fp16 HMMA, single-sync pipeline, 2 CTAs/SM)
    gemm16<<<dim3(C_/128, M_TOT/128, 3), 128, G16_SMEM>>>(nullptr, 1);

    // RoPE -> fp16 Q,K
    rope_split_kernel<<<(2 * BH_ * T_ * 64) / 256, 256>>>();

    // wo split
    split16_kernel<<<(nw4 + 255)/256, 256>>>((const float4*)wo, 4, nw4);

    // Attention
    attn_qk<<<dim3(3, BH_), 256, QK_SMEM>>>();
    softmax_p<<<(BH_ * T_) / 8, 256>>>();
    attn_pv<<<dim3(2, BH_), 256, PV_SMEM>>>();

    // Output projection
    gemm16<<<dim3(C_/128, M_TOT/128, 1), 128, G16_SMEM>>>(out, 0);
}

// round 11
// speedup vs baseline: 1.1680x; 1.0580x over previous
#include <cuda_runtime.h>
#include <cuda_bf16.h>
#include <cuda_fp16.h>
#include <cstdint>

#define B_  32
#define T_  256
#define C_  2048
#define H_  16
#define D_  128
#define M_TOT (B_*T_)     // 8192
#define BH_  (B_*H_)      // 512

// ------------------------------------------------------------------
// Device globals
// ------------------------------------------------------------------
__device__ float g_q[(size_t)BH_*T_*D_];
__device__ float g_k[(size_t)BH_*T_*D_];
__device__ float g_cos[T_*64];
__device__ float g_sin[T_*64];
__device__ __half g_x16[(size_t)M_TOT*C_];
__device__ __half g_w16[(size_t)4*C_*C_];
__device__ __half g_y16[(size_t)M_TOT*C_];
__device__ __half g_q16[(size_t)BH_*T_*D_];   // pre-scaled by 1/sqrt(D)
__device__ __half g_k16[(size_t)BH_*T_*D_];
__device__ __half g_v16[(size_t)BH_*T_*D_];

// ------------------------------------------------------------------
// PTX helpers
// ------------------------------------------------------------------
__device__ __forceinline__ uint32_t smem_u32(const void* p) {
    uint32_t a;
    asm("{ .reg .u64 t; cvta.to.shared.u64 t, %1; cvt.u32.u64 %0, t; }" : "=r"(a) : "l"(p));
    return a;
}
__device__ __forceinline__ uint32_t h2u(__half2 h) {
    return *reinterpret_cast<uint32_t*>(&h);
}
__device__ __forceinline__ void cp16(uint32_t dst, const void* src) {
    asm volatile("cp.async.cg.shared.global [%0], [%1], 16;" :: "r"(dst), "l"(src));
}
__device__ __forceinline__ void cp_commit() {
    asm volatile("cp.async.commit_group;" ::: "memory");
}
__device__ __forceinline__ void ldmx4(uint32_t* r, uint32_t addr) {
    asm volatile("ldmatrix.sync.aligned.m8n8.x4.shared.b16 {%0,%1,%2,%3}, [%4];"
                 : "=r"(r[0]), "=r"(r[1]), "=r"(r[2]), "=r"(r[3]) : "r"(addr));
}
__device__ __forceinline__ void ldmx4t(uint32_t* r, uint32_t addr) {
    asm volatile("ldmatrix.sync.aligned.m8n8.x4.trans.shared.b16 {%0,%1,%2,%3}, [%4];"
                 : "=r"(r[0]), "=r"(r[1]), "=r"(r[2]), "=r"(r[3]) : "r"(addr));
}
__device__ __forceinline__ void mma16816h(float* d, const uint32_t* a, const uint32_t* b) {
    asm volatile(
        "mma.sync.aligned.m16n8k16.row.col.f32.f16.f16.f32 "
        "{%0,%1,%2,%3}, {%4,%5,%6,%7}, {%8,%9}, {%0,%1,%2,%3};"
        : "+f"(d[0]), "+f"(d[1]), "+f"(d[2]), "+f"(d[3])
        : "r"(a[0]), "r"(a[1]), "r"(a[2]), "r"(a[3]), "r"(b[0]), "r"(b[1]));
}
// Swizzle for [rows][32 x 16-bit] tiles (64B rows)
__device__ __forceinline__ uint32_t swz(int r, int c) {
    return (uint32_t)(r * 64 + ((c ^ ((r >> 1) & 3)) << 4));
}
// Swizzle for [rows][64 x 16-bit] tiles (128B rows)
__device__ __forceinline__ uint32_t swz128(int r, int c) {
    return (uint32_t)(r * 128 + ((c ^ (r & 7)) << 4));
}

#define SCALE 0.08838834764831845f

// ------------------------------------------------------------------
// fp32 -> fp16 conversion (x)
// ------------------------------------------------------------------
__global__ __launch_bounds__(256)
void splitx_kernel(const float4* __restrict__ src, int n4)
{
    int i = blockIdx.x * 256 + threadIdx.x;
    if (i >= n4) return;
    float4 v = src[i];
    __half2* dp = (__half2*)g_x16;
    dp[2*i]   = __floats2half2_rn(v.x, v.y);
    dp[2*i+1] = __floats2half2_rn(v.z, v.w);
}

// all 4 weights in one launch: blockIdx.y selects the weight
__global__ __launch_bounds__(256)
void splitw_kernel(const float4* __restrict__ w0, const float4* __restrict__ w1,
                   const float4* __restrict__ w2, const float4* __restrict__ w3)
{
    int i = blockIdx.x * 256 + threadIdx.x;           // 0 .. C*C/4-1
    int s = blockIdx.y;
    const float4* src = (s == 0) ? w0 : (s == 1) ? w1 : (s == 2) ? w2 : w3;
    float4 v = src[i];
    __half2* dp = (__half2*)(g_w16 + (size_t)s * C_ * C_);
    dp[2*i]   = __floats2half2_rn(v.x, v.y);
    dp[2*i+1] = __floats2half2_rn(v.z, v.w);
}

// ------------------------------------------------------------------
// fp16 HMMA GEMM (R7 best config: 128 thr, 4 warps 64x64, 3 stages, 2 CTA/SM)
// ------------------------------------------------------------------
#define G16_STAGE 32768             // A 16KB | B 16KB
#define G16_SMEM (1024 + 3*G16_STAGE)

__global__ __launch_bounds__(128, 2)
void gemm16(float* __restrict__ Out, int mode)
{
    extern __shared__ char dsm[];
    const int tid  = threadIdx.x;
    const int wid  = tid >> 5;
    const int lane = tid & 31;
    const int bn = blockIdx.x * 128;
    const int bm = blockIdx.y * 128;
    const int wz = blockIdx.z;

    const __half* A_g = (mode == 0) ? g_y16 : g_x16;
    const int widx = (mode == 0) ? 3 : wz;
    const __half* B_g = g_w16 + (size_t)widx * C_ * C_;

    const uint32_t base = (smem_u32(dsm) + 1023u) & ~1023u;

    auto load_stage = [&](int kt, int s) {
        const uint32_t sb = base + (uint32_t)s * G16_STAGE;
        const int kb = kt * 64;
        #pragma unroll
        for (int it = 0; it < 8; it++) {
            int idx = tid + it * 128;
            int r = idx >> 3, c = idx & 7;
            uint32_t off = swz128(r, c);
            cp16(sb + off,         A_g + (size_t)(bm + r) * C_ + kb + c * 8);
            cp16(sb + 16384 + off, B_g + (size_t)(bn + r) * C_ + kb + c * 8);
        }
        cp_commit();
    };

    const int wm = (wid >> 1) * 64;
    const int wn = (wid & 1) * 64;
    const int arow = wm + (lane & 15);
    const int acol_base = (lane >> 4);
    const int brow = wn + (lane & 7) + ((lane & 16) >> 1);
    const int bcol_base = ((lane >> 3) & 1);

    float acc[4][8][4];
    #pragma unroll
    for (int i = 0; i < 4; i++)
        #pragma unroll
        for (int j = 0; j < 8; j++)
            #pragma unroll
            for (int q = 0; q < 4; q++) acc[i][j][q] = 0.0f;

    const int NK = C_ / 64;

    load_stage(0, 0);
    load_stage(1, 1);

    for (int c = 0; c < NK; c++) {
        __syncthreads();
        if (c + 2 < NK) load_stage(c + 2, (c + 2) % 3);
        else            cp_commit();
        asm volatile("cp.async.wait_group 2;" ::: "memory");
        __syncthreads();

        const uint32_t sA = base + (uint32_t)(c % 3) * G16_STAGE;
        const uint32_t sB = sA + 16384;

        #pragma unroll
        for (int ks = 0; ks < 4; ks++) {
            uint32_t ah[4][4];
            #pragma unroll
            for (int mt = 0; mt < 4; mt++)
                ldmx4(ah[mt], sA + swz128(arow + mt * 16, ks * 2 + acol_base));
            uint32_t bh[8][2];
            #pragma unroll
            for (int ng = 0; ng < 4; ng++) {
                uint32_t q[4];
                ldmx4(q, sB + swz128(brow + ng * 16, ks * 2 + bcol_base));
                bh[2*ng][0] = q[0]; bh[2*ng][1] = q[1];
                bh[2*ng+1][0] = q[2]; bh[2*ng+1][1] = q[3];
            }
            #pragma unroll
            for (int mt = 0; mt < 4; mt++)
                #pragma unroll
                for (int nt = 0; nt < 8; nt++)
                    mma16816h(acc[mt][nt], ah[mt], bh[nt]);
        }
    }

    float* qkv = (wz == 0) ? g_q : g_k;
    #pragma unroll
    for (int mt = 0; mt < 4; mt++) {
        const int row0 = bm + wm + mt * 16 + (lane >> 2);
        #pragma unroll
        for (int nt = 0; nt < 8; nt++) {
            const int col = bn + wn + nt * 8 + (lane & 3) * 2;
            #pragma unroll
            for (int half = 0; half < 2; half++) {
                const int row = row0 + half * 8;
                float y0 = acc[mt][nt][half * 2 + 0];
                float y1 = acc[mt][nt][half * 2 + 1];
                if (mode == 0) {
                    float2 v; v.x = y0; v.y = y1;
                    *(float2*)(Out + (size_t)row * C_ + col) = v;
                } else {
                    const int b = row >> 8, t = row & 255;
                    const int h = col >> 7, d0 = col & 127;
                    const size_t ix = (((size_t)b * H_ + h) * T_ + t) * D_ + d0;
                    if (wz < 2) {
                        float2 v; v.x = y0; v.y = y1;
                        *(float2*)(qkv + ix) = v;
                    } else {
                        *(__half2*)(g_v16 + ix) = __floats2half2_rn(y0, y1);
                    }
                }
            }
        }
    }
}

// ------------------------------------------------------------------
// RoPE tables + application (Q pre-scaled by 1/sqrt(D))
// ------------------------------------------------------------------
__global__ void rope_table_kernel()
{
    int idx = blockIdx.x * blockDim.x + threadIdx.x;
    if (idx >= T_ * 64) return;
    int j = idx & 63;
    int t = idx >> 6;
    double inv = exp(-(double)j * (9.210340371976184 / 64.0));
    double th = (double)t * inv;
    g_cos[idx] = (float)cos(th);
    g_sin[idx] = (float)sin(th);
}

__global__ __launch_bounds__(256)
void rope_split_kernel()
{
    int idx = blockIdx.x * 256 + threadIdx.x;
    int j = idx & 63;
    int t = (idx >> 6) & 255;
    int rest = idx >> 14;
    int bh = rest & 511;
    int isK = rest >> 9;
    const float* src = (isK ? g_k : g_q) + ((size_t)bh * T_ + t) * D_ + j;
    float c = g_cos[t * 64 + j];
    float s = g_sin[t * 64 + j];
    float x0 = src[0], x1 = src[64];
    float r0 = x0 * c - x1 * s;
    float r1 = x1 * c + x0 * s;
    if (!isK) { r0 *= SCALE; r1 *= SCALE; }
    __half* dh = isK ? g_k16 : g_q16;
    const size_t bx = ((size_t)bh * T_ + t) * D_ + j;
    dh[bx]      = __float2half(r0);
    dh[bx + 64] = __float2half(r1);
}

// ------------------------------------------------------------------
// Fused flash attention. KT = number of 128-key tiles (1 for q-rows
// 0..127, 2 for q-rows 128..255). One CTA per bh. 8 warps; each warp
// owns 16 q-rows x all keys; softmax fully in registers.
// smem: Q[4][128][32] | K[4][KT*128][32] | V[KT*128][136] (272B pitch)
// ------------------------------------------------------------------
#define AF_SQ 0
#define AF_SK 32768
#define AF_SV (32768 + 65536)
#define AF_SMEM (1024 + AF_SV + 256*272)

template<int KT>
__global__ __launch_bounds__(256, 1)
void attn_fused()
{
    extern __shared__ char dsm[];
    const int tid  = threadIdx.x;
    const int w    = tid >> 5;
    const int lane = tid & 31;
    const int bh   = blockIdx.x;
    const int qt   = KT - 1;                 // 0 or 1

    const __half* Qg = g_q16 + ((size_t)bh * T_ + qt * 128) * D_;
    const __half* Kg = g_k16 + (size_t)bh * T_ * D_;
    const __half* Vg = g_v16 + (size_t)bh * T_ * D_;

    const uint32_t base = (smem_u32(dsm) + 1023u) & ~1023u;
    const uint32_t sQ = base + AF_SQ;
    const uint32_t sK = base + AF_SK;
    const uint32_t sV = base + AF_SV;

    // ---- loads ----
    #pragma unroll
    for (int it = 0; it < 8; it++) {                 // Q: 2048 chunks
        int idx = tid + it * 256;
        int r = idx >> 4, d16 = idx & 15;
        int c = d16 >> 2, ic = d16 & 3;
        cp16(sQ + (uint32_t)c * 8192 + swz(r, ic), Qg + (size_t)r * D_ + d16 * 8);
    }
    #pragma unroll
    for (int it = 0; it < KT * 8; it++) {            // K: KT*2048 chunks
        int idx = tid + it * 256;
        int r = idx >> 4, d16 = idx & 15;
        int c = d16 >> 2, ic = d16 & 3;
        cp16(sK + (uint32_t)c * 16384 + swz(r, ic), Kg + (size_t)r * D_ + d16 * 8);
    }
    #pragma unroll
    for (int it = 0; it < KT * 8; it++) {            // V: KT*2048 chunks
        int idx = tid + it * 256;
        int r = idx >> 4, dc = idx & 15;
        cp16(sV + (uint32_t)r * 272 + dc * 16, Vg + (size_t)r * D_ + dc * 8);
    }
    cp_commit();
    asm volatile("cp.async.wait_group 0;" ::: "memory");
    __syncthreads();

    // ---- S = Q K^T ----
    const int NT = KT * 16;                          // n8 key tiles
    const int arow = 16 * w + (lane & 15);
    const int acol_base = (lane >> 4);
    const int brow_l = (lane & 7) + ((lane & 16) >> 1);
    const int bcol_base = ((lane >> 3) & 1);

    float acc[NT][4];
    #pragma unroll
    for (int i = 0; i < NT; i++)
        #pragma unroll
        for (int q = 0; q < 4; q++) acc[i][q] = 0.0f;

    #pragma unroll
    for (int c4 = 0; c4 < 4; c4++) {
        #pragma unroll
        for (int ks = 0; ks < 2; ks++) {
            uint32_t qa[4];
            ldmx4(qa, sQ + (uint32_t)c4 * 8192 + swz(arow, ks * 2 + acol_base));
            #pragma unroll
            for (int g = 0; g < KT * 8; g++) {
                uint32_t bb[4];
                ldmx4(bb, sK + (uint32_t)c4 * 16384 + swz(g * 16 + brow_l, ks * 2 + bcol_base));
                mma16816h(acc[2*g],   qa, bb);
                mma16816h(acc[2*g+1], qa, bb + 2);
            }
        }
    }

    // ---- causal mask + softmax (rows r and r+8 per lane) ----
    const int row_lo = qt * 128 + 16 * w + (lane >> 2);
    const int row_hi = row_lo + 8;
    const float NEG = -1e30f;
    #pragma unroll
    for (int nt = 0; nt < NT; nt++) {
        const int col0 = nt * 8 + (lane & 3) * 2;
        if (col0     > row_lo) acc[nt][0] = NEG;
        if (col0 + 1 > row_lo) acc[nt][1] = NEG;
        if (col0     > row_hi) acc[nt][2] = NEG;
        if (col0 + 1 > row_hi) acc[nt][3] = NEG;
    }
    float mlo = NEG, mhi = NEG;
    #pragma unroll
    for (int nt = 0; nt < NT; nt++) {
        mlo = fmaxf(mlo, fmaxf(acc[nt][0], acc[nt][1]));
        mhi = fmaxf(mhi, fmaxf(acc[nt][2], acc[nt][3]));
    }
    mlo = fmaxf(mlo, __shfl_xor_sync(0xffffffffu, mlo, 1));
    mlo = fmaxf(mlo, __shfl_xor_sync(0xffffffffu, mlo, 2));
    mhi = fmaxf(mhi, __shfl_xor_sync(0xffffffffu, mhi, 1));
    mhi = fmaxf(mhi, __shfl_xor_sync(0xffffffffu, mhi, 2));
    float slo = 0.f, shi = 0.f;
    #pragma unroll
    for (int nt = 0; nt < NT; nt++) {
        acc[nt][0] = __expf(acc[nt][0] - mlo);
        acc[nt][1] = __expf(acc[nt][1] - mlo);
        acc[nt][2] = __expf(acc[nt][2] - mhi);
        acc[nt][3] = __expf(acc[nt][3] - mhi);
        slo += acc[nt][0] + acc[nt][1];
        shi += acc[nt][2] + acc[nt][3];
    }
    slo += __shfl_xor_sync(0xffffffffu, slo, 1);
    slo += __shfl_xor_sync(0xffffffffu, slo, 2);
    shi += __shfl_xor_sync(0xffffffffu, shi, 1);
    shi += __shfl_xor_sync(0xffffffffu, shi, 2);
    const float ilo = 1.0f / slo;
    const float ihi = 1.0f / shi;

    // ---- pack P into A-fragments (k = key dim) ----
    uint32_t pf[KT * 8][4];
    #pragma unroll
    for (int j = 0; j < KT * 8; j++) {
        pf[j][0] = h2u(__floats2half2_rn(acc[2*j][0] * ilo, acc[2*j][1] * ilo));
        pf[j][1] = h2u(__floats2half2_rn(acc[2*j][2] * ihi, acc[2*j][3] * ihi));
        pf[j][2] = h2u(__floats2half2_rn(acc[2*j+1][0] * ilo, acc[2*j+1][1] * ilo));
        pf[j][3] = h2u(__floats2half2_rn(acc[2*j+1][2] * ihi, acc[2*j+1][3] * ihi));
    }

    // ---- O = P V ----
    const int kl_part = ((lane >> 3) & 1) * 8 + (lane & 7);
    const int nblk = lane >> 4;

    float oacc[16][4];
    #pragma unroll
    for (int i = 0; i < 16; i++)
        #pragma unroll
        for (int q = 0; q < 4; q++) oacc[i][q] = 0.0f;

    #pragma unroll
    for (int j = 0; j < KT * 8; j++) {
        #pragma unroll
        for (int dp = 0; dp < 8; dp++) {
            uint32_t bb[4];
            ldmx4t(bb, sV + (uint32_t)(j * 16 + kl_part) * 272 + (uint32_t)(dp * 2 + nblk) * 16);
            mma16816h(oacc[2*dp],   pf[j], bb);
            mma16816h(oacc[2*dp+1], pf[j], bb + 2);
        }
    }

    // ---- epilogue: y fp16 [B, T, C] ----
    const int b = bh >> 4, h = bh & 15;
    #pragma unroll
    for (int nt = 0; nt < 16; nt++) {
        const int d = nt * 8 + (lane & 3) * 2;
        const size_t ix_lo = ((size_t)b * T_ + row_lo) * C_ + h * D_ + d;
        const size_t ix_hi = ((size_t)b * T_ + row_hi) * C_ + h * D_ + d;
        *(__half2*)(g_y16 + ix_lo) = __floats2half2_rn(oacc[nt][0], oacc[nt][1]);
        *(__half2*)(g_y16 + ix_hi) = __floats2half2_rn(oacc[nt][2], oacc[nt][3]);
    }
}

// ------------------------------------------------------------------
extern "C" void kernel_launch(void* const* d_in, const int* in_sizes, int n_in,
                              void* d_out, int out_size)
{
    const float* x  = (const float*)d_in[0];
    const float* wq = (const float*)d_in[1];
    const float* wk = (const float*)d_in[2];
    const float* wv = (const float*)d_in[3];
    const float* wo = (const float*)d_in[4];
    float* out = (float*)d_out;

    const int nx4 = M_TOT * C_ / 4;
    const int nw4 = C_ * C_ / 4;

    cudaFuncSetAttribute(gemm16, cudaFuncAttributeMaxDynamicSharedMemorySize, G16_SMEM);
    cudaFuncSetAttribute(attn_fused<1>, cudaFuncAttributeMaxDynamicSharedMemorySize, AF_SMEM);
    cudaFuncSetAttribute(attn_fused<2>, cudaFuncAttributeMaxDynamicSharedMemorySize, AF_SMEM);

    // conversions
    splitx_kernel<<<(nx4 + 255)/256, 256>>>((const float4*)x, nx4);
    splitw_kernel<<<dim3(nw4/256, 4), 256>>>((const float4*)wq, (const float4*)wk,
                                             (const float4*)wv, (const float4*)wo);
    rope_table_kernel<<<(T_*64 + 255)/256, 256>>>();

    // QKV projections
    gemm16<<<dim3(C_/128, M_TOT/128, 3), 128, G16_SMEM>>>(nullptr, 1);

    // RoPE -> fp16 Q (pre-scaled), K
    rope_split_kernel<<<(2 * BH_ * T_ * 64) / 256, 256>>>();

    // fused attention (two causal shapes)
    attn_fused<2><<<BH_, 256, AF_SMEM>>>();
    attn_fused<1><<<BH_, 256, AF_SMEM>>>();

    // Output projection
    gemm16<<<dim3(C_/128, M_TOT/128, 1), 128, G16_SMEM>>>(out, 0);
}

// round 12
// speedup vs baseline: 1.1823x; 1.0123x over previous
#include <cuda_runtime.h>
#include <cuda_bf16.h>
#include <cuda_fp16.h>
#include <cstdint>

#define B_  32
#define T_  256
#define C_  2048
#define H_  16
#define D_  128
#define M_TOT (B_*T_)     // 8192
#define BH_  (B_*H_)      // 512

// ------------------------------------------------------------------
// Device globals
// ------------------------------------------------------------------
__device__ float g_cos[T_*64];
__device__ float g_sin[T_*64];
__device__ __half g_x16[(size_t)M_TOT*C_];
__device__ __half g_w16[(size_t)4*C_*C_];
__device__ __half g_y16[(size_t)M_TOT*C_];
__device__ __half g_qp[(size_t)BH_*T_*D_];    // pre-rope Q (fp16)
__device__ __half g_kp[(size_t)BH_*T_*D_];    // pre-rope K (fp16)
__device__ __half g_q16[(size_t)BH_*T_*D_];   // roped Q, pre-scaled by 1/sqrt(D)
__device__ __half g_k16[(size_t)BH_*T_*D_];   // roped K
__device__ __half g_v16[(size_t)BH_*T_*D_];

// ------------------------------------------------------------------
// PTX helpers
// ------------------------------------------------------------------
__device__ __forceinline__ uint32_t smem_u32(const void* p) {
    uint32_t a;
    asm("{ .reg .u64 t; cvta.to.shared.u64 t, %1; cvt.u32.u64 %0, t; }" : "=r"(a) : "l"(p));
    return a;
}
__device__ __forceinline__ uint32_t h2u(__half2 h) {
    return *reinterpret_cast<uint32_t*>(&h);
}
__device__ __forceinline__ void cp16(uint32_t dst, const void* src) {
    asm volatile("cp.async.cg.shared.global [%0], [%1], 16;" :: "r"(dst), "l"(src));
}
__device__ __forceinline__ void cp_commit() {
    asm volatile("cp.async.commit_group;" ::: "memory");
}
__device__ __forceinline__ void ldmx4(uint32_t* r, uint32_t addr) {
    asm volatile("ldmatrix.sync.aligned.m8n8.x4.shared.b16 {%0,%1,%2,%3}, [%4];"
                 : "=r"(r[0]), "=r"(r[1]), "=r"(r[2]), "=r"(r[3]) : "r"(addr));
}
__device__ __forceinline__ void ldmx4t(uint32_t* r, uint32_t addr) {
    asm volatile("ldmatrix.sync.aligned.m8n8.x4.trans.shared.b16 {%0,%1,%2,%3}, [%4];"
                 : "=r"(r[0]), "=r"(r[1]), "=r"(r[2]), "=r"(r[3]) : "r"(addr));
}
__device__ __forceinline__ void mma16816h(float* d, const uint32_t* a, const uint32_t* b) {
    asm volatile(
        "mma.sync.aligned.m16n8k16.row.col.f32.f16.f16.f32 "
        "{%0,%1,%2,%3}, {%4,%5,%6,%7}, {%8,%9}, {%0,%1,%2,%3};"
        : "+f"(d[0]), "+f"(d[1]), "+f"(d[2]), "+f"(d[3])
        : "r"(a[0]), "r"(a[1]), "r"(a[2]), "r"(a[3]), "r"(b[0]), "r"(b[1]));
}
// Swizzle for [rows][32 x 16-bit] tiles (64B rows)
__device__ __forceinline__ uint32_t swz(int r, int c) {
    return (uint32_t)(r * 64 + ((c ^ ((r >> 1) & 3)) << 4));
}
// Swizzle for [rows][64 x 16-bit] tiles (128B rows)
__device__ __forceinline__ uint32_t swz128(int r, int c) {
    return (uint32_t)(r * 128 + ((c ^ (r & 7)) << 4));
}

#define SCALE 0.08838834764831845f

// ------------------------------------------------------------------
// fp32 -> fp16 conversion (x)
// ------------------------------------------------------------------
__global__ __launch_bounds__(256)
void splitx_kernel(const float4* __restrict__ src, int n4)
{
    int i = blockIdx.x * 256 + threadIdx.x;
    if (i >= n4) return;
    float4 v = src[i];
    __half2* dp = (__half2*)g_x16;
    dp[2*i]   = __floats2half2_rn(v.x, v.y);
    dp[2*i+1] = __floats2half2_rn(v.z, v.w);
}

// all 4 weights in one launch: blockIdx.y selects the weight
__global__ __launch_bounds__(256)
void splitw_kernel(const float4* __restrict__ w0, const float4* __restrict__ w1,
                   const float4* __restrict__ w2, const float4* __restrict__ w3)
{
    int i = blockIdx.x * 256 + threadIdx.x;
    int s = blockIdx.y;
    const float4* src = (s == 0) ? w0 : (s == 1) ? w1 : (s == 2) ? w2 : w3;
    float4 v = src[i];
    __half2* dp = (__half2*)(g_w16 + (size_t)s * C_ * C_);
    dp[2*i]   = __floats2half2_rn(v.x, v.y);
    dp[2*i+1] = __floats2half2_rn(v.z, v.w);
}

// ------------------------------------------------------------------
// fp16 HMMA GEMM (128 thr, 4 warps 64x64, 3 stages, 2 CTA/SM)
// mode 1: x @ w{q,k,v}^T -> g_qp/g_kp/g_v16 fp16 [B,H,T,D]
// mode 0: y @ wo^T -> Out fp32 [M, C]
// ------------------------------------------------------------------
#define G16_STAGE 32768             // A 16KB | B 16KB
#define G16_SMEM (1024 + 3*G16_STAGE)

__global__ __launch_bounds__(128, 2)
void gemm16(float* __restrict__ Out, int mode)
{
    extern __shared__ char dsm[];
    const int tid  = threadIdx.x;
    const int wid  = tid >> 5;
    const int lane = tid & 31;
    const int bn = blockIdx.x * 128;
    const int bm = blockIdx.y * 128;
    const int wz = blockIdx.z;

    const __half* A_g = (mode == 0) ? g_y16 : g_x16;
    const int widx = (mode == 0) ? 3 : wz;
    const __half* B_g = g_w16 + (size_t)widx * C_ * C_;

    const uint32_t base = (smem_u32(dsm) + 1023u) & ~1023u;

    auto load_stage = [&](int kt, int s) {
        const uint32_t sb = base + (uint32_t)s * G16_STAGE;
        const int kb = kt * 64;
        #pragma unroll
        for (int it = 0; it < 8; it++) {
            int idx = tid + it * 128;
            int r = idx >> 3, c = idx & 7;
            uint32_t off = swz128(r, c);
            cp16(sb + off,         A_g + (size_t)(bm + r) * C_ + kb + c * 8);
            cp16(sb + 16384 + off, B_g + (size_t)(bn + r) * C_ + kb + c * 8);
        }
        cp_commit();
    };

    const int wm = (wid >> 1) * 64;
    const int wn = (wid & 1) * 64;
    const int arow = wm + (lane & 15);
    const int acol_base = (lane >> 4);
    const int brow = wn + (lane & 7) + ((lane & 16) >> 1);
    const int bcol_base = ((lane >> 3) & 1);

    float acc[4][8][4];
    #pragma unroll
    for (int i = 0; i < 4; i++)
        #pragma unroll
        for (int j = 0; j < 8; j++)
            #pragma unroll
            for (int q = 0; q < 4; q++) acc[i][j][q] = 0.0f;

    const int NK = C_ / 64;

    load_stage(0, 0);
    load_stage(1, 1);

    for (int c = 0; c < NK; c++) {
        __syncthreads();
        if (c + 2 < NK) load_stage(c + 2, (c + 2) % 3);
        else            cp_commit();
        asm volatile("cp.async.wait_group 2;" ::: "memory");
        __syncthreads();

        const uint32_t sA = base + (uint32_t)(c % 3) * G16_STAGE;
        const uint32_t sB = sA + 16384;

        #pragma unroll
        for (int ks = 0; ks < 4; ks++) {
            uint32_t ah[4][4];
            #pragma unroll
            for (int mt = 0; mt < 4; mt++)
                ldmx4(ah[mt], sA + swz128(arow + mt * 16, ks * 2 + acol_base));
            uint32_t bh[8][2];
            #pragma unroll
            for (int ng = 0; ng < 4; ng++) {
                uint32_t q[4];
                ldmx4(q, sB + swz128(brow + ng * 16, ks * 2 + bcol_base));
                bh[2*ng][0] = q[0]; bh[2*ng][1] = q[1];
                bh[2*ng+1][0] = q[2]; bh[2*ng+1][1] = q[3];
            }
            #pragma unroll
            for (int mt = 0; mt < 4; mt++)
                #pragma unroll
                for (int nt = 0; nt < 8; nt++)
                    mma16816h(acc[mt][nt], ah[mt], bh[nt]);
        }
    }

    __half* qkv = (wz == 0) ? g_qp : (wz == 1) ? g_kp : g_v16;
    #pragma unroll
    for (int mt = 0; mt < 4; mt++) {
        const int row0 = bm + wm + mt * 16 + (lane >> 2);
        #pragma unroll
        for (int nt = 0; nt < 8; nt++) {
            const int col = bn + wn + nt * 8 + (lane & 3) * 2;
            #pragma unroll
            for (int half = 0; half < 2; half++) {
                const int row = row0 + half * 8;
                float y0 = acc[mt][nt][half * 2 + 0];
                float y1 = acc[mt][nt][half * 2 + 1];
                if (mode == 0) {
                    float2 v; v.x = y0; v.y = y1;
                    *(float2*)(Out + (size_t)row * C_ + col) = v;
                } else {
                    const int b = row >> 8, t = row & 255;
                    const int h = col >> 7, d0 = col & 127;
                    const size_t ix = (((size_t)b * H_ + h) * T_ + t) * D_ + d0;
                    *(__half2*)(qkv + ix) = __floats2half2_rn(y0, y1);
                }
            }
        }
    }
}

// ------------------------------------------------------------------
// RoPE tables + application (fp16 in, fp16 out; Q pre-scaled)
// ------------------------------------------------------------------
__global__ void rope_table_kernel()
{
    int idx = blockIdx.x * blockDim.x + threadIdx.x;
    if (idx >= T_ * 64) return;
    int j = idx & 63;
    int t = idx >> 6;
    double inv = exp(-(double)j * (9.210340371976184 / 64.0));
    double th = (double)t * inv;
    g_cos[idx] = (float)cos(th);
    g_sin[idx] = (float)sin(th);
}

__global__ __launch_bounds__(256)
void rope_split_kernel()
{
    int idx = blockIdx.x * 256 + threadIdx.x;
    int j = idx & 63;
    int t = (idx >> 6) & 255;
    int rest = idx >> 14;
    int bh = rest & 511;
    int isK = rest >> 9;
    const __half* src = (isK ? g_kp : g_qp) + ((size_t)bh * T_ + t) * D_ + j;
    float c = g_cos[t * 64 + j];
    float s = g_sin[t * 64 + j];
    float x0 = __half2float(src[0]), x1 = __half2float(src[64]);
    float r0 = x0 * c - x1 * s;
    float r1 = x1 * c + x0 * s;
    if (!isK) { r0 *= SCALE; r1 *= SCALE; }
    __half* dh = isK ? g_k16 : g_q16;
    const size_t bx = ((size_t)bh * T_ + t) * D_ + j;
    dh[bx]      = __float2half(r0);
    dh[bx + 64] = __float2half(r1);
}

// ------------------------------------------------------------------
// Fused flash attention (unchanged from R11)
// ------------------------------------------------------------------
#define AF_SQ 0
#define AF_SK 32768
#define AF_SV (32768 + 65536)
#define AF_SMEM (1024 + AF_SV + 256*272)

template<int KT>
__global__ __launch_bounds__(256, 1)
void attn_fused()
{
    extern __shared__ char dsm[];
    const int tid  = threadIdx.x;
    const int w    = tid >> 5;
    const int lane = tid & 31;
    const int bh   = blockIdx.x;
    const int qt   = KT - 1;

    const __half* Qg = g_q16 + ((size_t)bh * T_ + qt * 128) * D_;
    const __half* Kg = g_k16 + (size_t)bh * T_ * D_;
    const __half* Vg = g_v16 + (size_t)bh * T_ * D_;

    const uint32_t base = (smem_u32(dsm) + 1023u) & ~1023u;
    const uint32_t sQ = base + AF_SQ;
    const uint32_t sK = base + AF_SK;
    const uint32_t sV = base + AF_SV;

    #pragma unroll
    for (int it = 0; it < 8; it++) {
        int idx = tid + it * 256;
        int r = idx >> 4, d16 = idx & 15;
        int c = d16 >> 2, ic = d16 & 3;
        cp16(sQ + (uint32_t)c * 8192 + swz(r, ic), Qg + (size_t)r * D_ + d16 * 8);
    }
    #pragma unroll
    for (int it = 0; it < KT * 8; it++) {
        int idx = tid + it * 256;
        int r = idx >> 4, d16 = idx & 15;
        int c = d16 >> 2, ic = d16 & 3;
        cp16(sK + (uint32_t)c * 16384 + swz(r, ic), Kg + (size_t)r * D_ + d16 * 8);
    }
    #pragma unroll
    for (int it = 0; it < KT * 8; it++) {
        int idx = tid + it * 256;
        int r = idx >> 4, dc = idx & 15;
        cp16(sV + (uint32_t)r * 272 + dc * 16, Vg + (size_t)r * D_ + dc * 8);
    }
    cp_commit();
    asm volatile("cp.async.wait_group 0;" ::: "memory");
    __syncthreads();

    const int NT = KT * 16;
    const int arow = 16 * w + (lane & 15);
    const int acol_base = (lane >> 4);
    const int brow_l = (lane & 7) + ((lane & 16) >> 1);
    const int bcol_base = ((lane >> 3) & 1);

    float acc[NT][4];
    #pragma unroll
    for (int i = 0; i < NT; i++)
        #pragma unroll
        for (int q = 0; q < 4; q++) acc[i][q] = 0.0f;

    #pragma unroll
    for (int c4 = 0; c4 < 4; c4++) {
        #pragma unroll
        for (int ks = 0; ks < 2; ks++) {
            uint32_t qa[4];
            ldmx4(qa, sQ + (uint32_t)c4 * 8192 + swz(arow, ks * 2 + acol_base));
            #pragma unroll
            for (int g = 0; g < KT * 8; g++) {
                uint32_t bb[4];
                ldmx4(bb, sK + (uint32_t)c4 * 16384 + swz(g * 16 + brow_l, ks * 2 + bcol_base));
                mma16816h(acc[2*g],   qa, bb);
                mma16816h(acc[2*g+1], qa, bb + 2);
            }
        }
    }

    const int row_lo = qt * 128 + 16 * w + (lane >> 2);
    const int row_hi = row_lo + 8;
    const float NEG = -1e30f;
    #pragma unroll
    for (int nt = 0; nt < NT; nt++) {
        const int col0 = nt * 8 + (lane & 3) * 2;
        if (col0     > row_lo) acc[nt][0] = NEG;
        if (col0 + 1 > row_lo) acc[nt][1] = NEG;
        if (col0     > row_hi) acc[nt][2] = NEG;
        if (col0 + 1 > row_hi) acc[nt][3] = NEG;
    }
    float mlo = NEG, mhi = NEG;
    #pragma unroll
    for (int nt = 0; nt < NT; nt++) {
        mlo = fmaxf(mlo, fmaxf(acc[nt][0], acc[nt][1]));
        mhi = fmaxf(mhi, fmaxf(acc[nt][2], acc[nt][3]));
    }
    mlo = fmaxf(mlo, __shfl_xor_sync(0xffffffffu, mlo, 1));
    mlo = fmaxf(mlo, __shfl_xor_sync(0xffffffffu, mlo, 2));
    mhi = fmaxf(mhi, __shfl_xor_sync(0xffffffffu, mhi, 1));
    mhi = fmaxf(mhi, __shfl_xor_sync(0xffffffffu, mhi, 2));
    float slo = 0.f, shi = 0.f;
    #pragma unroll
    for (int nt = 0; nt < NT; nt++) {
        acc[nt][0] = __expf(acc[nt][0] - mlo);
        acc[nt][1] = __expf(acc[nt][1] - mlo);
        acc[nt][2] = __expf(acc[nt][2] - mhi);
        acc[nt][3] = __expf(acc[nt][3] - mhi);
        slo += acc[nt][0] + acc[nt][1];
        shi += acc[nt][2] + acc[nt][3];
    }
    slo += __shfl_xor_sync(0xffffffffu, slo, 1);
    slo += __shfl_xor_sync(0xffffffffu, slo, 2);
    shi += __shfl_xor_sync(0xffffffffu, shi, 1);
    shi += __shfl_xor_sync(0xffffffffu, shi, 2);
    const float ilo = 1.0f / slo;
    const float ihi = 1.0f / shi;

    uint32_t pf[KT * 8][4];
    #pragma unroll
    for (int j = 0; j < KT * 8; j++) {
        pf[j][0] = h2u(__floats2half2_rn(acc[2*j][0] * ilo, acc[2*j][1] * ilo));
        pf[j][1] = h2u(__floats2half2_rn(acc[2*j][2] * ihi, acc[2*j][3] * ihi));
        pf[j][2] = h2u(__floats2half2_rn(acc[2*j+1][0] * ilo, acc[2*j+1][1] * ilo));
        pf[j][3] = h2u(__floats2half2_rn(acc[2*j+1][2] * ihi, acc[2*j+1][3] * ihi));
    }

    const int kl_part = ((lane >> 3) & 1) * 8 + (lane & 7);
    const int nblk = lane >> 4;

    float oacc[16][4];
    #pragma unroll
    for (int i = 0; i < 16; i++)
        #pragma unroll
        for (int q = 0; q < 4; q++) oacc[i][q] = 0.0f;

    #pragma unroll
    for (int j = 0; j < KT * 8; j++) {
        #pragma unroll
        for (int dp = 0; dp < 8; dp++) {
            uint32_t bb[4];
            ldmx4t(bb, sV + (uint32_t)(j * 16 + kl_part) * 272 + (uint32_t)(dp * 2 + nblk) * 16);
            mma16816h(oacc[2*dp],   pf[j], bb);
            mma16816h(oacc[2*dp+1], pf[j], bb + 2);
        }
    }

    const int b = bh >> 4, h = bh & 15;
    #pragma unroll
    for (int nt = 0; nt < 16; nt++) {
        const int d = nt * 8 + (lane & 3) * 2;
        const size_t ix_lo = ((size_t)b * T_ + row_lo) * C_ + h * D_ + d;
        const size_t ix_hi = ((size_t)b * T_ + row_hi) * C_ + h * D_ + d;
        *(__half2*)(g_y16 + ix_lo) = __floats2half2_rn(oacc[nt][0], oacc[nt][1]);
        *(__half2*)(g_y16 + ix_hi) = __floats2half2_rn(oacc[nt][2], oacc[nt][3]);
    }
}

// ------------------------------------------------------------------
extern "C" void kernel_launch(void* const* d_in, const int* in_sizes, int n_in,
                              void* d_out, int out_size)
{
    const float* x  = (const float*)d_in[0];
    const float* wq = (const float*)d_in[1];
    const float* wk = (const float*)d_in[2];
    const float* wv = (const float*)d_in[3];
    const float* wo = (const float*)d_in[4];
    float* out = (float*)d_out;

    const int nx4 = M_TOT * C_ / 4;
    const int nw4 = C_ * C_ / 4;

    cudaFuncSetAttribute(gemm16, cudaFuncAttributeMaxDynamicSharedMemorySize, G16_SMEM);
    cudaFuncSetAttribute(attn_fused<1>, cudaFuncAttributeMaxDynamicSharedMemorySize, AF_SMEM);
    cudaFuncSetAttribute(attn_fused<2>, cudaFuncAttributeMaxDynamicSharedMemorySize, AF_SMEM);

    // conversions
    splitx_kernel<<<(nx4 + 255)/256, 256>>>((const float4*)x, nx4);
    splitw_kernel<<<dim3(nw4/256, 4), 256>>>((const float4*)wq, (const float4*)wk,
                                             (const float4*)wv, (const float4*)wo);
    rope_table_kernel<<<(T_*64 + 255)/256, 256>>>();

    // QKV projections (launch #4)
    gemm16<<<dim3(C_/128, M_TOT/128, 3), 128, G16_SMEM>>>(nullptr, 1);

    // RoPE (fp16 -> fp16)
    rope_split_kernel<<<(2 * BH_ * T_ * 64) / 256, 256>>>();

    // fused attention
    attn_fused<2><<<BH_, 256, AF_SMEM>>>();
    attn_fused<1><<<BH_, 256, AF_SMEM>>>();

    // Output projection
    gemm16<<<dim3(C_/128, M_TOT/128, 1), 128, G16_SMEM>>>(out, 0);
}

// round 13
// speedup vs baseline: 1.2452x; 1.0532x over previous
#include <cuda_runtime.h>
#include <cuda_bf16.h>
#include <cuda_fp16.h>
#include <cstdint>

#define B_  32
#define T_  256
#define C_  2048
#define H_  16
#define D_  128
#define M_TOT (B_*T_)     // 8192
#define BH_  (B_*H_)      // 512

// ------------------------------------------------------------------
// Device globals
// ------------------------------------------------------------------
__device__ float g_cos[T_*64];
__device__ float g_sin[T_*64];
__device__ __half g_x16[(size_t)M_TOT*C_];
__device__ __half g_w16[(size_t)4*C_*C_];
__device__ __half g_y16[(size_t)M_TOT*C_];
__device__ __half g_qp[(size_t)BH_*T_*D_];    // pre-rope Q (fp16)
__device__ __half g_kp[(size_t)BH_*T_*D_];    // pre-rope K (fp16)
__device__ __half g_v16[(size_t)BH_*T_*D_];

// ------------------------------------------------------------------
// PTX helpers
// ------------------------------------------------------------------
__device__ __forceinline__ uint32_t smem_u32(const void* p) {
    uint32_t a;
    asm("{ .reg .u64 t; cvta.to.shared.u64 t, %1; cvt.u32.u64 %0, t; }" : "=r"(a) : "l"(p));
    return a;
}
__device__ __forceinline__ uint32_t h2u(__half2 h) {
    return *reinterpret_cast<uint32_t*>(&h);
}
__device__ __forceinline__ void cp16(uint32_t dst, const void* src) {
    asm volatile("cp.async.cg.shared.global [%0], [%1], 16;" :: "r"(dst), "l"(src));
}
__device__ __forceinline__ void cp_commit() {
    asm volatile("cp.async.commit_group;" ::: "memory");
}
__device__ __forceinline__ void sts128(uint32_t addr, uint32_t r0, uint32_t r1, uint32_t r2, uint32_t r3) {
    asm volatile("st.shared.v4.b32 [%0], {%1,%2,%3,%4};"
                 :: "r"(addr), "r"(r0), "r"(r1), "r"(r2), "r"(r3) : "memory");
}
__device__ __forceinline__ void ldmx4(uint32_t* r, uint32_t addr) {
    asm volatile("ldmatrix.sync.aligned.m8n8.x4.shared.b16 {%0,%1,%2,%3}, [%4];"
                 : "=r"(r[0]), "=r"(r[1]), "=r"(r[2]), "=r"(r[3]) : "r"(addr));
}
__device__ __forceinline__ void ldmx4t(uint32_t* r, uint32_t addr) {
    asm volatile("ldmatrix.sync.aligned.m8n8.x4.trans.shared.b16 {%0,%1,%2,%3}, [%4];"
                 : "=r"(r[0]), "=r"(r[1]), "=r"(r[2]), "=r"(r[3]) : "r"(addr));
}
__device__ __forceinline__ void mma16816h(float* d, const uint32_t* a, const uint32_t* b) {
    asm volatile(
        "mma.sync.aligned.m16n8k16.row.col.f32.f16.f16.f32 "
        "{%0,%1,%2,%3}, {%4,%5,%6,%7}, {%8,%9}, {%0,%1,%2,%3};"
        : "+f"(d[0]), "+f"(d[1]), "+f"(d[2]), "+f"(d[3])
        : "r"(a[0]), "r"(a[1]), "r"(a[2]), "r"(a[3]), "r"(b[0]), "r"(b[1]));
}
// Swizzle for [rows][32 x 16-bit] tiles (64B rows)
__device__ __forceinline__ uint32_t swz(int r, int c) {
    return (uint32_t)(r * 64 + ((c ^ ((r >> 1) & 3)) << 4));
}
// Swizzle for [rows][64 x 16-bit] tiles (128B rows)
__device__ __forceinline__ uint32_t swz128(int r, int c) {
    return (uint32_t)(r * 128 + ((c ^ (r & 7)) << 4));
}

#define SCALE 0.08838834764831845f

// ------------------------------------------------------------------
// fp32 -> fp16 conversion (x)
// ------------------------------------------------------------------
__global__ __launch_bounds__(256)
void splitx_kernel(const float4* __restrict__ src, int n4)
{
    int i = blockIdx.x * 256 + threadIdx.x;
    if (i >= n4) return;
    float4 v = src[i];
    __half2* dp = (__half2*)g_x16;
    dp[2*i]   = __floats2half2_rn(v.x, v.y);
    dp[2*i+1] = __floats2half2_rn(v.z, v.w);
}

// all 4 weights in one launch: blockIdx.y selects the weight
__global__ __launch_bounds__(256)
void splitw_kernel(const float4* __restrict__ w0, const float4* __restrict__ w1,
                   const float4* __restrict__ w2, const float4* __restrict__ w3)
{
    int i = blockIdx.x * 256 + threadIdx.x;
    int s = blockIdx.y;
    const float4* src = (s == 0) ? w0 : (s == 1) ? w1 : (s == 2) ? w2 : w3;
    float4 v = src[i];
    __half2* dp = (__half2*)(g_w16 + (size_t)s * C_ * C_);
    dp[2*i]   = __floats2half2_rn(v.x, v.y);
    dp[2*i+1] = __floats2half2_rn(v.z, v.w);
}

// ------------------------------------------------------------------
// fp16 HMMA GEMM (128 thr, 4 warps 64x64, 3 stages, 2 CTA/SM)
// ------------------------------------------------------------------
#define G16_STAGE 32768             // A 16KB | B 16KB
#define G16_SMEM (1024 + 3*G16_STAGE)

__global__ __launch_bounds__(128, 2)
void gemm16(float* __restrict__ Out, int mode)
{
    extern __shared__ char dsm[];
    const int tid  = threadIdx.x;
    const int wid  = tid >> 5;
    const int lane = tid & 31;
    const int bn = blockIdx.x * 128;
    const int bm = blockIdx.y * 128;
    const int wz = blockIdx.z;

    const __half* A_g = (mode == 0) ? g_y16 : g_x16;
    const int widx = (mode == 0) ? 3 : wz;
    const __half* B_g = g_w16 + (size_t)widx * C_ * C_;

    const uint32_t base = (smem_u32(dsm) + 1023u) & ~1023u;

    auto load_stage = [&](int kt, int s) {
        const uint32_t sb = base + (uint32_t)s * G16_STAGE;
        const int kb = kt * 64;
        #pragma unroll
        for (int it = 0; it < 8; it++) {
            int idx = tid + it * 128;
            int r = idx >> 3, c = idx & 7;
            uint32_t off = swz128(r, c);
            cp16(sb + off,         A_g + (size_t)(bm + r) * C_ + kb + c * 8);
            cp16(sb + 16384 + off, B_g + (size_t)(bn + r) * C_ + kb + c * 8);
        }
        cp_commit();
    };

    const int wm = (wid >> 1) * 64;
    const int wn = (wid & 1) * 64;
    const int arow = wm + (lane & 15);
    const int acol_base = (lane >> 4);
    const int brow = wn + (lane & 7) + ((lane & 16) >> 1);
    const int bcol_base = ((lane >> 3) & 1);

    float acc[4][8][4];
    #pragma unroll
    for (int i = 0; i < 4; i++)
        #pragma unroll
        for (int j = 0; j < 8; j++)
            #pragma unroll
            for (int q = 0; q < 4; q++) acc[i][j][q] = 0.0f;

    const int NK = C_ / 64;

    load_stage(0, 0);
    load_stage(1, 1);

    for (int c = 0; c < NK; c++) {
        __syncthreads();
        if (c + 2 < NK) load_stage(c + 2, (c + 2) % 3);
        else            cp_commit();
        asm volatile("cp.async.wait_group 2;" ::: "memory");
        __syncthreads();

        const uint32_t sA = base + (uint32_t)(c % 3) * G16_STAGE;
        const uint32_t sB = sA + 16384;

        #pragma unroll
        for (int ks = 0; ks < 4; ks++) {
            uint32_t ah[4][4];
            #pragma unroll
            for (int mt = 0; mt < 4; mt++)
                ldmx4(ah[mt], sA + swz128(arow + mt * 16, ks * 2 + acol_base));
            uint32_t bh[8][2];
            #pragma unroll
            for (int ng = 0; ng < 4; ng++) {
                uint32_t q[4];
                ldmx4(q, sB + swz128(brow + ng * 16, ks * 2 + bcol_base));
                bh[2*ng][0] = q[0]; bh[2*ng][1] = q[1];
                bh[2*ng+1][0] = q[2]; bh[2*ng+1][1] = q[3];
            }
            #pragma unroll
            for (int mt = 0; mt < 4; mt++)
                #pragma unroll
                for (int nt = 0; nt < 8; nt++)
                    mma16816h(acc[mt][nt], ah[mt], bh[nt]);
        }
    }

    __half* qkv = (wz == 0) ? g_qp : (wz == 1) ? g_kp : g_v16;
    #pragma unroll
    for (int mt = 0; mt < 4; mt++) {
        const int row0 = bm + wm + mt * 16 + (lane >> 2);
        #pragma unroll
        for (int nt = 0; nt < 8; nt++) {
            const int col = bn + wn + nt * 8 + (lane & 3) * 2;
            #pragma unroll
            for (int half = 0; half < 2; half++) {
                const int row = row0 + half * 8;
                float y0 = acc[mt][nt][half * 2 + 0];
                float y1 = acc[mt][nt][half * 2 + 1];
                if (mode == 0) {
                    float2 v; v.x = y0; v.y = y1;
                    *(float2*)(Out + (size_t)row * C_ + col) = v;
                } else {
                    const int b = row >> 8, t = row & 255;
                    const int h = col >> 7, d0 = col & 127;
                    const size_t ix = (((size_t)b * H_ + h) * T_ + t) * D_ + d0;
                    *(__half2*)(qkv + ix) = __floats2half2_rn(y0, y1);
                }
            }
        }
    }
}

// ------------------------------------------------------------------
// RoPE tables
// ------------------------------------------------------------------
__global__ void rope_table_kernel()
{
    int idx = blockIdx.x * blockDim.x + threadIdx.x;
    if (idx >= T_ * 64) return;
    int j = idx & 63;
    int t = idx >> 6;
    double inv = exp(-(double)j * (9.210340371976184 / 64.0));
    double th = (double)t * inv;
    g_cos[idx] = (float)cos(th);
    g_sin[idx] = (float)sin(th);
}

// ------------------------------------------------------------------
// Fused flash attention with in-kernel RoPE on Q and K.
// KT = number of 128-key tiles. One CTA per bh.
// smem: Q[4][128][32] | K[4][KT*128][32] | V[KT*128][136] (272B pitch)
// ------------------------------------------------------------------
#define AF_SQ 0
#define AF_SK 32768
#define AF_SV (32768 + 65536)
#define AF_SMEM (1024 + AF_SV + 256*272)

template<int KT>
__global__ __launch_bounds__(256, 1)
void attn_fused()
{
    extern __shared__ char dsm[];
    const int tid  = threadIdx.x;
    const int w    = tid >> 5;
    const int lane = tid & 31;
    const int bh   = blockIdx.x;
    const int qt   = KT - 1;

    const __half* Qg = g_qp + ((size_t)bh * T_ + qt * 128) * D_;
    const __half* Kg = g_kp + (size_t)bh * T_ * D_;
    const __half* Vg = g_v16 + (size_t)bh * T_ * D_;

    const uint32_t base = (smem_u32(dsm) + 1023u) & ~1023u;
    const uint32_t sQ = base + AF_SQ;
    const uint32_t sK = base + AF_SK;
    const uint32_t sV = base + AF_SV;

    // ---- V via cp.async first (overlaps with rope work below) ----
    #pragma unroll
    for (int it = 0; it < KT * 8; it++) {
        int idx = tid + it * 256;
        int r = idx >> 4, dc = idx & 15;
        cp16(sV + (uint32_t)r * 272 + dc * 16, Vg + (size_t)r * D_ + dc * 8);
    }
    cp_commit();

    // ---- Q with RoPE (+1/sqrt(D)): pair chunks d=j8*8 and d+64 ----
    #pragma unroll
    for (int it = 0; it < 4; it++) {
        int idx = tid + it * 256;               // 0..1023
        int r = idx >> 3, j8 = idx & 7;
        const __half* src = Qg + (size_t)r * D_ + j8 * 8;
        uint4 lo = *(const uint4*)(src);
        uint4 hi = *(const uint4*)(src + 64);
        const int tg = qt * 128 + r;
        const float4 c0 = *(const float4*)(g_cos + tg * 64 + j8 * 8);
        const float4 c1 = *(const float4*)(g_cos + tg * 64 + j8 * 8 + 4);
        const float4 s0 = *(const float4*)(g_sin + tg * 64 + j8 * 8);
        const float4 s1 = *(const float4*)(g_sin + tg * 64 + j8 * 8 + 4);
        const float cc[8] = {c0.x, c0.y, c0.z, c0.w, c1.x, c1.y, c1.z, c1.w};
        const float ss[8] = {s0.x, s0.y, s0.z, s0.w, s1.x, s1.y, s1.z, s1.w};
        uint32_t olo[4], ohi[4];
        #pragma unroll
        for (int i = 0; i < 4; i++) {
            float2 x0 = __half22float2(((const __half2*)&lo)[i]);
            float2 x1 = __half22float2(((const __half2*)&hi)[i]);
            float a0 = (x0.x * cc[2*i]   - x1.x * ss[2*i])   * SCALE;
            float a1 = (x0.y * cc[2*i+1] - x1.y * ss[2*i+1]) * SCALE;
            float b0 = (x1.x * cc[2*i]   + x0.x * ss[2*i])   * SCALE;
            float b1 = (x1.y * cc[2*i+1] + x0.y * ss[2*i+1]) * SCALE;
            olo[i] = h2u(__floats2half2_rn(a0, a1));
            ohi[i] = h2u(__floats2half2_rn(b0, b1));
        }
        const uint32_t a_lo = sQ + (uint32_t)(j8 >> 2) * 8192 + swz(r, j8 & 3);
        const uint32_t a_hi = sQ + (uint32_t)(2 + (j8 >> 2)) * 8192 + swz(r, j8 & 3);
        sts128(a_lo, olo[0], olo[1], olo[2], olo[3]);
        sts128(a_hi, ohi[0], ohi[1], ohi[2], ohi[3]);
    }

    // ---- K with RoPE (no scale) ----
    #pragma unroll
    for (int it = 0; it < KT * 4; it++) {
        int idx = tid + it * 256;               // 0..KT*1024-1
        int r = idx >> 3, j8 = idx & 7;
        const __half* src = Kg + (size_t)r * D_ + j8 * 8;
        uint4 lo = *(const uint4*)(src);
        uint4 hi = *(const uint4*)(src + 64);
        const float4 c0 = *(const float4*)(g_cos + r * 64 + j8 * 8);
        const float4 c1 = *(const float4*)(g_cos + r * 64 + j8 * 8 + 4);
        const float4 s0 = *(const float4*)(g_sin + r * 64 + j8 * 8);
        const float4 s1 = *(const float4*)(g_sin + r * 64 + j8 * 8 + 4);
        const float cc[8] = {c0.x, c0.y, c0.z, c0.w, c1.x, c1.y, c1.z, c1.w};
        const float ss[8] = {s0.x, s0.y, s0.z, s0.w, s1.x, s1.y, s1.z, s1.w};
        uint32_t olo[4], ohi[4];
        #pragma unroll
        for (int i = 0; i < 4; i++) {
            float2 x0 = __half22float2(((const __half2*)&lo)[i]);
            float2 x1 = __half22float2(((const __half2*)&hi)[i]);
            float a0 = x0.x * cc[2*i]   - x1.x * ss[2*i];
            float a1 = x0.y * cc[2*i+1] - x1.y * ss[2*i+1];
            float b0 = x1.x * cc[2*i]   + x0.x * ss[2*i];
            float b1 = x1.y * cc[2*i+1] + x0.y * ss[2*i+1];
            olo[i] = h2u(__floats2half2_rn(a0, a1));
            ohi[i] = h2u(__floats2half2_rn(b0, b1));
        }
        const uint32_t a_lo = sK + (uint32_t)(j8 >> 2) * 16384 + swz(r, j8 & 3);
        const uint32_t a_hi = sK + (uint32_t)(2 + (j8 >> 2)) * 16384 + swz(r, j8 & 3);
        sts128(a_lo, olo[0], olo[1], olo[2], olo[3]);
        sts128(a_hi, ohi[0], ohi[1], ohi[2], ohi[3]);
    }

    asm volatile("cp.async.wait_group 0;" ::: "memory");
    __syncthreads();

    // ---- S = Q K^T ----
    const int NT = KT * 16;
    const int arow = 16 * w + (lane & 15);
    const int acol_base = (lane >> 4);
    const int brow_l = (lane & 7) + ((lane & 16) >> 1);
    const int bcol_base = ((lane >> 3) & 1);

    float acc[NT][4];
    #pragma unroll
    for (int i = 0; i < NT; i++)
        #pragma unroll
        for (int q = 0; q < 4; q++) acc[i][q] = 0.0f;

    #pragma unroll
    for (int c4 = 0; c4 < 4; c4++) {
        #pragma unroll
        for (int ks = 0; ks < 2; ks++) {
            uint32_t qa[4];
            ldmx4(qa, sQ + (uint32_t)c4 * 8192 + swz(arow, ks * 2 + acol_base));
            #pragma unroll
            for (int g = 0; g < KT * 8; g++) {
                uint32_t bb[4];
                ldmx4(bb, sK + (uint32_t)c4 * 16384 + swz(g * 16 + brow_l, ks * 2 + bcol_base));
                mma16816h(acc[2*g],   qa, bb);
                mma16816h(acc[2*g+1], qa, bb + 2);
            }
        }
    }

    // ---- causal mask + softmax ----
    const int row_lo = qt * 128 + 16 * w + (lane >> 2);
    const int row_hi = row_lo + 8;
    const float NEG = -1e30f;
    #pragma unroll
    for (int nt = 0; nt < NT; nt++) {
        const int col0 = nt * 8 + (lane & 3) * 2;
        if (col0     > row_lo) acc[nt][0] = NEG;
        if (col0 + 1 > row_lo) acc[nt][1] = NEG;
        if (col0     > row_hi) acc[nt][2] = NEG;
        if (col0 + 1 > row_hi) acc[nt][3] = NEG;
    }
    float mlo = NEG, mhi = NEG;
    #pragma unroll
    for (int nt = 0; nt < NT; nt++) {
        mlo = fmaxf(mlo, fmaxf(acc[nt][0], acc[nt][1]));
        mhi = fmaxf(mhi, fmaxf(acc[nt][2], acc[nt][3]));
    }
    mlo = fmaxf(mlo, __shfl_xor_sync(0xffffffffu, mlo, 1));
    mlo = fmaxf(mlo, __shfl_xor_sync(0xffffffffu, mlo, 2));
    mhi = fmaxf(mhi, __shfl_xor_sync(0xffffffffu, mhi, 1));
    mhi = fmaxf(mhi, __shfl_xor_sync(0xffffffffu, mhi, 2));
    float slo = 0.f, shi = 0.f;
    #pragma unroll
    for (int nt = 0; nt < NT; nt++) {
        acc[nt][0] = __expf(acc[nt][0] - mlo);
        acc[nt][1] = __expf(acc[nt][1] - mlo);
        acc[nt][2] = __expf(acc[nt][2] - mhi);
        acc[nt][3] = __expf(acc[nt][3] - mhi);
        slo += acc[nt][0] + acc[nt][1];
        shi += acc[nt][2] + acc[nt][3];
    }
    slo += __shfl_xor_sync(0xffffffffu, slo, 1);
    slo += __shfl_xor_sync(0xffffffffu, slo, 2);
    shi += __shfl_xor_sync(0xffffffffu, shi, 1);
    shi += __shfl_xor_sync(0xffffffffu, shi, 2);
    const float ilo = 1.0f / slo;
    const float ihi = 1.0f / shi;

    uint32_t pf[KT * 8][4];
    #pragma unroll
    for (int j = 0; j < KT * 8; j++) {
        pf[j][0] = h2u(__floats2half2_rn(acc[2*j][0] * ilo, acc[2*j][1] * ilo));
        pf[j][1] = h2u(__floats2half2_rn(acc[2*j][2] * ihi, acc[2*j][3] * ihi));
        pf[j][2] = h2u(__floats2half2_rn(acc[2*j+1][0] * ilo, acc[2*j+1][1] * ilo));
        pf[j][3] = h2u(__floats2half2_rn(acc[2*j+1][2] * ihi, acc[2*j+1][3] * ihi));
    }

    // ---- O = P V ----
    const int kl_part = ((lane >> 3) & 1) * 8 + (lane & 7);
    const int nblk = lane >> 4;

    float oacc[16][4];
    #pragma unroll
    for (int i = 0; i < 16; i++)
        #pragma unroll
        for (int q = 0; q < 4; q++) oacc[i][q] = 0.0f;

    #pragma unroll
    for (int j = 0; j < KT * 8; j++) {
        #pragma unroll
        for (int dp = 0; dp < 8; dp++) {
            uint32_t bb[4];
            ldmx4t(bb, sV + (uint32_t)(j * 16 + kl_part) * 272 + (uint32_t)(dp * 2 + nblk) * 16);
            mma16816h(oacc[2*dp],   pf[j], bb);
            mma16816h(oacc[2*dp+1], pf[j], bb + 2);
        }
    }

    // ---- epilogue: y fp16 [B, T, C] ----
    const int b = bh >> 4, h = bh & 15;
    #pragma unroll
    for (int nt = 0; nt < 16; nt++) {
        const int d = nt * 8 + (lane & 3) * 2;
        const size_t ix_lo = ((size_t)b * T_ + row_lo) * C_ + h * D_ + d;
        const size_t ix_hi = ((size_t)b * T_ + row_hi) * C_ + h * D_ + d;
        *(__half2*)(g_y16 + ix_lo) = __floats2half2_rn(oacc[nt][0], oacc[nt][1]);
        *(__half2*)(g_y16 + ix_hi) = __floats2half2_rn(oacc[nt][2], oacc[nt][3]);
    }
}

// ------------------------------------------------------------------
extern "C" void kernel_launch(void* const* d_in, const int* in_sizes, int n_in,
                              void* d_out, int out_size)
{
    const float* x  = (const float*)d_in[0];
    const float* wq = (const float*)d_in[1];
    const float* wk = (const float*)d_in[2];
    const float* wv = (const float*)d_in[3];
    const float* wo = (const float*)d_in[4];
    float* out = (float*)d_out;

    const int nx4 = M_TOT * C_ / 4;
    const int nw4 = C_ * C_ / 4;

    cudaFuncSetAttribute(gemm16, cudaFuncAttributeMaxDynamicSharedMemorySize, G16_SMEM);
    cudaFuncSetAttribute(attn_fused<1>, cudaFuncAttributeMaxDynamicSharedMemorySize, AF_SMEM);
    cudaFuncSetAttribute(attn_fused<2>, cudaFuncAttributeMaxDynamicSharedMemorySize, AF_SMEM);

    // conversions + rope tables
    splitx_kernel<<<(nx4 + 255)/256, 256>>>((const float4*)x, nx4);
    splitw_kernel<<<dim3(nw4/256, 4), 256>>>((const float4*)wq, (const float4*)wk,
                                             (const float4*)wv, (const float4*)wo);
    rope_table_kernel<<<(T_*64 + 255)/256, 256>>>();

    // QKV projections
    gemm16<<<dim3(C_/128, M_TOT/128, 3), 128, G16_SMEM>>>(nullptr, 1);

    // fused attention (rope applied in-kernel)
    attn_fused<2><<<BH_, 256, AF_SMEM>>>();
    attn_fused<1><<<BH_, 256, AF_SMEM>>>();

    // Output projection
    gemm16<<<dim3(C_/128, M_TOT/128, 1), 128, G16_SMEM>>>(out, 0);
}